// round 14
// baseline (speedup 1.0000x reference)
#include <cuda_runtime.h>
#include <cuda_fp16.h>
#include <cstdint>
#include <cstddef>

// Problem constants
#define NROWS 65536   // 64*32*32 flat rows
#define KC    1024    // codes
#define DIM   256     // embedding dim
#define HW    1024    // 32*32

// Output packing (tuple order, all float32)
#define OUT_ZQ   0ull
#define OUT_LOSS 16777216ull
#define OUT_IDX  16777217ull
#define OUT_CB   16842753ull
#define OUT_CS   17104897ull
#define OUT_DW   17105921ull

#define NSLOT  48
#define MARGIN 6e-3f

// int8 quantization scales (validated R13)
#define INV_SF   (127.0f / 5.5f)
#define CODE_Q   130048.0f                  // 1024*127 (codes in +-1/1024)
#define SCALE    (5.5f / (127.0f * 130048.0f))  // sf * sc

// Scratch (device globals: no allocations allowed)
__device__ float   g_c2[KC];
__device__ int     g_idx[NROWS];
__device__ int     g_counts[KC];
__device__ double  g_loss;
__device__ int     g_rand[KC];
__device__ float   g_smooth[KC];
__device__ int     g_dead[KC];
__device__ int     g_ccnt[NROWS];
__device__ int     g_cand[NROWS * NSLOT];
__device__ int     g_cbi[16 * 64 * 64];      // int8-packed codebook, tile-major
__device__ float   g_flat[(size_t)NROWS * DIM];  // transposed z (64 MB)
__device__ int     g_off[KC];
__device__ int     g_cursor[KC];
__device__ int     g_rows[NROWS];

// ===========================================================================
#define CP_ASYNC16(dst, src) \
    asm volatile("cp.async.ca.shared.global [%0], [%1], 16;" :: "r"(dst), "l"(src))
#define CP_COMMIT()  asm volatile("cp.async.commit_group;" ::: "memory")
#define CP_WAIT0()   asm volatile("cp.async.wait_group 0;" ::: "memory")

__device__ __forceinline__ uint32_t smem_to_u32(const void* p) {
    uint32_t a;
    asm("{ .reg .u64 t; cvta.to.shared.u64 t, %1; cvt.u32.u64 %0, t; }"
        : "=r"(a) : "l"(p));
    return a;
}

__device__ __forceinline__ int q8(float v, float s) {
    float x = v * s;
    x = fminf(fmaxf(x, -127.0f), 127.0f);
    return __float2int_rn(x);
}

// ===========================================================================
// k_cbt: codebook -> int8 tile layout + scratch init.
// g_cbi[t*4096 + d4*64 + code] packs dims 4*d4..4*d4+3 of code (t*64+code).
__global__ void k_cbt(const float* __restrict__ cb) {
    int idx = blockIdx.x * 256 + threadIdx.x;        // 256 blocks -> 65536
    int t = idx >> 12, rem = idx & 4095;
    int d4 = rem >> 6, code = rem & 63;
    const float* src = cb + (size_t)(t * 64 + code) * DIM + 4 * d4;
    int b0 = q8(src[0], CODE_Q) & 255;
    int b1 = q8(src[1], CODE_Q) & 255;
    int b2 = q8(src[2], CODE_Q) & 255;
    int b3 = q8(src[3], CODE_Q) & 255;
    g_cbi[idx] = b0 | (b1 << 8) | (b2 << 16) | (b3 << 24);
    // fused init
    g_ccnt[idx] = 0;                                 // idx spans exactly NROWS
    if (idx < KC) g_counts[idx] = 0;
    if (idx == 0) g_loss = 0.0;
}

// c2[k] = sum_d fl(cb[k][d]^2), sequential in-order fp32 (XLA CPU naive reduce)
__global__ void k_c2(const float* __restrict__ cb) {
    int k = blockIdx.x * blockDim.x + threadIdx.x;
    if (k >= KC) return;
    const float* row = cb + (size_t)k * DIM;
    float s = 0.0f;
    for (int d = 0; d < DIM; ++d) {
        float v = row[d];
        s = __fadd_rn(s, __fmul_rn(v, v));
    }
    g_c2[k] = s;
}

// Exact JAX threefry2x32 for key(1)
__device__ __forceinline__ uint32_t tf_rotl(uint32_t v, int r) {
    return (v << r) | (v >> (32 - r));
}
__global__ void k_rng() {
    int i = threadIdx.x;
    if (i >= 512) return;
    const uint32_t ks0 = 0u, ks1 = 1u, ks2 = 0x1BD11BDBu;
    uint32_t x0 = (uint32_t)i + ks0;
    uint32_t x1 = (uint32_t)(i + 512) + ks1;
    const int ra[4] = {13, 15, 26, 6};
    const int rb[4] = {17, 29, 16, 24};
#define TF_R4(rots) { x0 += x1; x1 = tf_rotl(x1, rots[0]); x1 ^= x0; \
                      x0 += x1; x1 = tf_rotl(x1, rots[1]); x1 ^= x0; \
                      x0 += x1; x1 = tf_rotl(x1, rots[2]); x1 ^= x0; \
                      x0 += x1; x1 = tf_rotl(x1, rots[3]); x1 ^= x0; }
    TF_R4(ra); x0 += ks1; x1 += ks2 + 1u;
    TF_R4(rb); x0 += ks2; x1 += ks0 + 2u;
    TF_R4(ra); x0 += ks0; x1 += ks1 + 3u;
    TF_R4(rb); x0 += ks1; x1 += ks2 + 4u;
    TF_R4(ra); x0 += ks2; x1 += ks0 + 5u;
#undef TF_R4
    g_rand[i]       = (int)(x0 & 0xFFFFu);
    g_rand[i + 512] = (int)(x1 & 0xFFFFu);
}

// ===========================================================================
// k_filter: int8 dp4a approx GEMM, 4x4 register tile, running-min collection.
// CTA = 64 rows, 256 threads (q=row-quad 0..15, g=code-quad 0..15), 1024 CTAs.
// smem bytes:
//   s_flat int[64 d4][64 r]      @0       16384
//   s_code int[64 d4][68] x2     @16384   34816   (stride 68, 64 used; dbl buf)
//   s_c2   float[1024]           @51200    4096
#define OFF_CODE0 16384
#define OFF_CODE1 33792
#define OFF_C2F   51200
#define SMEM_FILT 55296

__global__ void __launch_bounds__(256, 3) k_filter(const float* __restrict__ z) {
    extern __shared__ char smraw[];
    signed char* s_flat_i8 = (signed char*)smraw;
    const int4*  s_flat_i4 = (const int4*)smraw;
    float* s_c2 = (float*)(smraw + OFF_C2F);
    const uint32_t uS = smem_to_u32(smraw);

    const int tid = threadIdx.x;
    const int g = tid & 15;        // code-group: codes 4g..4g+3 of tile
    const int q = tid >> 4;        // row-group : rows 4q..4q+3

    for (int i = tid; i < KC; i += 256) s_c2[i] = g_c2[i];

    const int n0 = blockIdx.x * 64;
    const int b = n0 >> 10, hw0 = n0 & 1023;
    const float* zb = z + (size_t)b * (DIM * HW) + hw0;

    // ---- stage flat tile quantized int8: byte at [d4*256 + r*4 + (d&3)]
    {
        int r = tid & 63, dchunk = tid >> 6;         // 4 chunks x 64 dims
#pragma unroll
        for (int i = 0; i < 64; ++i) {
            int d = dchunk * 64 + i;
            float v = zb[(size_t)d * HW + r];
            s_flat_i8[(d >> 2) * 256 + r * 4 + (d & 3)] =
                (signed char)q8(v, INV_SF);
        }
    }

    // ---- prologue: stage code tile 0 via cp.async (16KB -> stride-272 rows)
    {
        const int* srcb = g_cbi;
#pragma unroll
        for (int i = 0; i < 4; ++i) {
            int cidx = tid + 256 * i;                // 1024 chunks of 16B
            int d4 = cidx >> 4, seg = cidx & 15;
            CP_ASYNC16(uS + OFF_CODE0 + (uint32_t)(d4 * 272 + seg * 16),
                       srcb + d4 * 64 + seg * 4);
        }
        CP_COMMIT();
    }

    float runm[4];
#pragma unroll
    for (int a = 0; a < 4; ++a) runm[a] = 3.4e38f;

#pragma unroll
    for (int t = 0; t < 16; ++t) {
        CP_WAIT0();
        __syncthreads();
        if (t < 15) {   // stage next tile into other buffer
            const int* srcb = g_cbi + (t + 1) * 4096;
            uint32_t dstb = uS + (((t + 1) & 1) ? OFF_CODE1 : OFF_CODE0);
#pragma unroll
            for (int i = 0; i < 4; ++i) {
                int cidx = tid + 256 * i;
                int d4 = cidx >> 4, seg = cidx & 15;
                CP_ASYNC16(dstb + (uint32_t)(d4 * 272 + seg * 16),
                           srcb + d4 * 64 + seg * 4);
            }
            CP_COMMIT();
        }

        const int4* s_code_i4 =
            (const int4*)(smraw + ((t & 1) ? OFF_CODE1 : OFF_CODE0));

        int acc[4][4];
#pragma unroll
        for (int a = 0; a < 4; ++a)
#pragma unroll
            for (int c = 0; c < 4; ++c) acc[a][c] = 0;

        // 64 d4-steps (4 dims each): exact int32 dp4a, 4 rows x 4 codes
#pragma unroll 16
        for (int d4 = 0; d4 < 64; ++d4) {
            int4 fa = s_flat_i4[d4 * 16 + q];        // rows 4q..4q+3
            int4 cc = s_code_i4[d4 * 17 + g];        // codes 4g..4g+3
            acc[0][0] = __dp4a(fa.x, cc.x, acc[0][0]);
            acc[0][1] = __dp4a(fa.x, cc.y, acc[0][1]);
            acc[0][2] = __dp4a(fa.x, cc.z, acc[0][2]);
            acc[0][3] = __dp4a(fa.x, cc.w, acc[0][3]);
            acc[1][0] = __dp4a(fa.y, cc.x, acc[1][0]);
            acc[1][1] = __dp4a(fa.y, cc.y, acc[1][1]);
            acc[1][2] = __dp4a(fa.y, cc.z, acc[1][2]);
            acc[1][3] = __dp4a(fa.y, cc.w, acc[1][3]);
            acc[2][0] = __dp4a(fa.z, cc.x, acc[2][0]);
            acc[2][1] = __dp4a(fa.z, cc.y, acc[2][1]);
            acc[2][2] = __dp4a(fa.z, cc.z, acc[2][2]);
            acc[2][3] = __dp4a(fa.z, cc.w, acc[2][3]);
            acc[3][0] = __dp4a(fa.w, cc.x, acc[3][0]);
            acc[3][1] = __dp4a(fa.w, cc.y, acc[3][1]);
            acc[3][2] = __dp4a(fa.w, cc.z, acc[3][2]);
            acc[3][3] = __dp4a(fa.w, cc.w, acc[3][3]);
        }

        // ---- epilogue: s = c2[k] - 2*SCALE*acc ; running-min; collect now.
        // thr uses running min so far -> >= final threshold -> superset (valid).
        int kb = t * 64 + 4 * g;
#pragma unroll
        for (int a = 0; a < 4; ++a) {
            float s0 = fmaf(-2.0f * SCALE, (float)acc[a][0], s_c2[kb + 0]);
            float s1 = fmaf(-2.0f * SCALE, (float)acc[a][1], s_c2[kb + 1]);
            float s2 = fmaf(-2.0f * SCALE, (float)acc[a][2], s_c2[kb + 2]);
            float s3 = fmaf(-2.0f * SCALE, (float)acc[a][3], s_c2[kb + 3]);
            float m = fminf(fminf(s0, s1), fminf(s2, s3));
            // tile-min across the 16 g-lanes (xor<16 stays in half-warp)
#pragma unroll
            for (int off = 1; off < 16; off <<= 1)
                m = fminf(m, __shfl_xor_sync(0xffffffffu, m, off));
            runm[a] = fminf(runm[a], m);
            float thr = runm[a] + MARGIN;
            int row = n0 + 4 * q + a;
            if (s0 <= thr) { int p = atomicAdd(&g_ccnt[row], 1); if (p < NSLOT) g_cand[row * NSLOT + p] = kb; }
            if (s1 <= thr) { int p = atomicAdd(&g_ccnt[row], 1); if (p < NSLOT) g_cand[row * NSLOT + p] = kb + 1; }
            if (s2 <= thr) { int p = atomicAdd(&g_ccnt[row], 1); if (p < NSLOT) g_cand[row * NSLOT + p] = kb + 2; }
            if (s3 <= thr) { int p = atomicAdd(&g_ccnt[row], 1); if (p < NSLOT) g_cand[row * NSLOT + p] = kb + 3; }
        }
    }
}

// ===========================================================================
// k_exact: block = 32 rows staged in smem (stride-33 pad); writes transposed
// g_flat; exact bitwise chains, f2 fused into first candidate chain (2x ILP);
// tie -> lowest k. 2048 x 256.
__global__ void __launch_bounds__(256) k_exact(const float* __restrict__ z,
                                               const float* __restrict__ cb) {
    __shared__ float s_z[DIM * 33];          // [d*33 + r], 33.8 KB
    __shared__ float s_best[8 * 32];
    __shared__ int   s_bk[8 * 32];

    const int tid = threadIdx.x;
    const int n0 = blockIdx.x * 32;
    const int b = n0 >> 10, hw0 = n0 & 1023;
    const float* zb = z + (size_t)b * (DIM * HW) + hw0;

    // stage 32 rows x 256 dims (coalesced gmem, conflict-free smem)
    {
        int r = tid & 31, dg = tid >> 5;     // 8 d-groups
#pragma unroll
        for (int i = 0; i < 32; ++i) {
            int d = dg * 32 + i;
            s_z[d * 33 + r] = zb[(size_t)d * HW + r];
        }
    }
    __syncthreads();

    const int r = tid & 31, slot = tid >> 5;     // slot = warp id

    // write transposed flat copy: warp w -> rows 4w..4w+3
    {
        int w = slot;
#pragma unroll
        for (int rr = 0; rr < 4; ++rr) {
            int row = w * 4 + rr;
            float* dst = &g_flat[(size_t)(n0 + row) * DIM];
#pragma unroll
            for (int c = 0; c < 8; ++c)
                dst[c * 32 + r] = s_z[(c * 32 + r) * 33 + row];
        }
    }

    const int row = n0 + r;
    const int cN = g_ccnt[row];

    float best = 3.4e38f; int bk = 1 << 30;

    if (cN <= NSLOT) {
        float f2 = 0.0f;
        // peeled first candidate: f2 chain fused with dot chain (2 indep chains)
        if (slot < cN) {
            int k = g_cand[row * NSLOT + slot];
            const float4* ck4 = (const float4*)(cb + (size_t)k * DIM);
            float acc = 0.0f, f2a = 0.0f;
#pragma unroll 8
            for (int d4 = 0; d4 < DIM / 4; ++d4) {
                float4 c4 = ck4[d4];
                int d = d4 * 4;
                float v0 = s_z[(d + 0) * 33 + r];
                float v1 = s_z[(d + 1) * 33 + r];
                float v2 = s_z[(d + 2) * 33 + r];
                float v3 = s_z[(d + 3) * 33 + r];
                f2a = __fadd_rn(f2a, __fmul_rn(v0, v0));
                acc = __fmaf_rn(v0, c4.x, acc);
                f2a = __fadd_rn(f2a, __fmul_rn(v1, v1));
                acc = __fmaf_rn(v1, c4.y, acc);
                f2a = __fadd_rn(f2a, __fmul_rn(v2, v2));
                acc = __fmaf_rn(v2, c4.z, acc);
                f2a = __fadd_rn(f2a, __fmul_rn(v3, v3));
                acc = __fmaf_rn(v3, c4.w, acc);
            }
            f2 = f2a;
            float d2v = __fadd_rn(__fsub_rn(f2, 2.0f * acc), g_c2[k]);
            if (d2v < best || (d2v == best && k < bk)) { best = d2v; bk = k; }
        }
        for (int idx = slot + 8; idx < cN; idx += 8) {
            int k = g_cand[row * NSLOT + idx];
            const float4* ck4 = (const float4*)(cb + (size_t)k * DIM);
            float acc = 0.0f;
#pragma unroll 8
            for (int d4 = 0; d4 < DIM / 4; ++d4) {
                float4 c4 = ck4[d4];
                int d = d4 * 4;
                acc = __fmaf_rn(s_z[(d + 0) * 33 + r], c4.x, acc);
                acc = __fmaf_rn(s_z[(d + 1) * 33 + r], c4.y, acc);
                acc = __fmaf_rn(s_z[(d + 2) * 33 + r], c4.z, acc);
                acc = __fmaf_rn(s_z[(d + 3) * 33 + r], c4.w, acc);
            }
            float d2v = __fadd_rn(__fsub_rn(f2, 2.0f * acc), g_c2[k]);
            if (d2v < best || (d2v == best && k < bk)) { best = d2v; bk = k; }
        }
    } else {
        // overflow fallback: exact full scan (rare)
        float f2 = 0.0f;
        for (int k = slot; k < KC; k += 8) {
            const float4* ck4 = (const float4*)(cb + (size_t)k * DIM);
            float acc = 0.0f, f2a = 0.0f;
#pragma unroll 8
            for (int d4 = 0; d4 < DIM / 4; ++d4) {
                float4 c4 = ck4[d4];
                int d = d4 * 4;
                float v0 = s_z[(d + 0) * 33 + r];
                float v1 = s_z[(d + 1) * 33 + r];
                float v2 = s_z[(d + 2) * 33 + r];
                float v3 = s_z[(d + 3) * 33 + r];
                if (k < 8) {
                    f2a = __fadd_rn(f2a, __fmul_rn(v0, v0));
                    f2a = __fadd_rn(f2a, __fmul_rn(v1, v1));
                    f2a = __fadd_rn(f2a, __fmul_rn(v2, v2));
                    f2a = __fadd_rn(f2a, __fmul_rn(v3, v3));
                }
                acc = __fmaf_rn(v0, c4.x, acc);
                acc = __fmaf_rn(v1, c4.y, acc);
                acc = __fmaf_rn(v2, c4.z, acc);
                acc = __fmaf_rn(v3, c4.w, acc);
            }
            if (k < 8) f2 = f2a;
            float d2v = __fadd_rn(__fsub_rn(f2, 2.0f * acc), g_c2[k]);
            if (d2v < best || (d2v == best && k < bk)) { best = d2v; bk = k; }
        }
    }

    s_best[slot * 32 + r] = best;
    s_bk[slot * 32 + r]   = bk;
    __syncthreads();
    if (tid < 32) {
        float bb = 3.4e38f; int kk = 1 << 30;
#pragma unroll
        for (int s = 0; s < 8; ++s) {
            float v = s_best[s * 32 + tid];
            int   k = s_bk[s * 32 + tid];
            if (v < bb || (v == bb && k < kk)) { bb = v; kk = k; }
        }
        g_idx[n0 + tid] = kk;
        atomicAdd(&g_counts[kk], 1);
    }
}

// ===========================================================================
// k_pfx: exclusive prefix sum of g_counts -> g_off, g_cursor. 1 block x 1024.
__global__ void k_pfx() {
    __shared__ int tmp[KC];
    int k = threadIdx.x;
    int c = g_counts[k];
    tmp[k] = c;
    __syncthreads();
    for (int off = 1; off < KC; off <<= 1) {
        int v = (k >= off) ? tmp[k - off] : 0;
        __syncthreads();
        tmp[k] += v;
        __syncthreads();
    }
    g_off[k] = tmp[k] - c;
    g_cursor[k] = tmp[k] - c;
}

// k_fill: scatter row ids into per-code lists. 256 blocks x 256.
__global__ void k_fill() {
    int n = blockIdx.x * 256 + threadIdx.x;
    int k = g_idx[n];
    int pos = atomicAdd(&g_cursor[k], 1);
    g_rows[pos] = n;
}

// ===========================================================================
// k_scatter: z_q + indices outputs, commit-loss. (dw handled by gather.)
__global__ void __launch_bounds__(256) k_scatter(const float* __restrict__ z,
                                                 const float* __restrict__ cb,
                                                 float* __restrict__ out,
                                                 size_t osz) {
    int n  = blockIdx.x * 256 + threadIdx.x;
    int b  = n >> 10, hw = n & 1023;
    int k  = g_idx[n];
    if (OUT_IDX + (size_t)n < osz) out[OUT_IDX + n] = (float)k;

    const float*  zr   = z  + (size_t)b * DIM * HW + hw;
    float*        orow = out + OUT_ZQ + (size_t)b * DIM * HW + hw;
    const float4* cr   = (const float4*)(cb + (size_t)k * DIM);

    float ls = 0.0f;
#pragma unroll 4
    for (int d4 = 0; d4 < 64; ++d4) {
        float4 qv = cr[d4];
        int d = d4 * 4;
        float z0 = zr[(size_t)(d + 0) * HW];
        float z1 = zr[(size_t)(d + 1) * HW];
        float z2 = zr[(size_t)(d + 2) * HW];
        float z3 = zr[(size_t)(d + 3) * HW];
        orow[(size_t)(d + 0) * HW] = qv.x;
        orow[(size_t)(d + 1) * HW] = qv.y;
        orow[(size_t)(d + 2) * HW] = qv.z;
        orow[(size_t)(d + 3) * HW] = qv.w;
        float e0 = qv.x - z0, e1 = qv.y - z1, e2 = qv.z - z2, e3 = qv.w - z3;
        ls = fmaf(e0, e0, ls); ls = fmaf(e1, e1, ls);
        ls = fmaf(e2, e2, ls); ls = fmaf(e3, e3, ls);
    }

    for (int o = 16; o > 0; o >>= 1) ls += __shfl_down_sync(0xffffffffu, ls, o);
    __shared__ float ws[8];
    int lane = threadIdx.x & 31, w = threadIdx.x >> 5;
    if (lane == 0) ws[w] = ls;
    __syncthreads();
    if (threadIdx.x == 0) {
        float s = 0.0f;
#pragma unroll
        for (int i = 0; i < 8; ++i) s += ws[i];
        atomicAdd(&g_loss, (double)s);
    }
}

// ===========================================================================
__global__ void k_fin_a(const float* __restrict__ ema_cs,
                        float* __restrict__ out, size_t osz) {
    int k = threadIdx.x;
    float cs = __fadd_rn(__fmul_rn(0.99f, ema_cs[k]),
                         __fmul_rn(0.01f, (float)g_counts[k]));
    __shared__ float red[1024];
    red[k] = cs;
    __syncthreads();
    for (int o = 512; o > 0; o >>= 1) {
        if (k < o) red[k] += red[k + o];
        __syncthreads();
    }
    float n = red[0];
    float smv = (cs + 1e-5f) / (n + 1024.0f * 1e-5f) * n;
    g_smooth[k] = smv;
    int dead = cs < 1.0f;
    g_dead[k] = dead;
    if (OUT_CS + (size_t)k < osz) out[OUT_CS + k] = dead ? 1.0f : cs;
    if (k == 0 && OUT_LOSS < osz)
        out[OUT_LOSS] = (float)(0.5 * g_loss / 16777216.0);
}

// ===========================================================================
// k_fin_b: gather dw[k] = sum over rows assigned to k (coalesced g_flat reads)
__global__ void k_fin_b(const float* __restrict__ ema_dw,
                        const float* __restrict__ z,
                        float* __restrict__ out, size_t osz) {
    int k = blockIdx.x;      // 1024
    int d = threadIdx.x;     // 256
    int off = g_off[k], cnt = g_counts[k];
    float s = 0.0f;
    for (int i = 0; i < cnt; ++i) {
        int n = g_rows[off + i];
        s += g_flat[(size_t)n * DIM + d];
    }
    size_t e = (size_t)k * DIM + d;
    float dwe = __fadd_rn(__fmul_rn(0.99f, ema_dw[e]),
                          __fmul_rn(0.01f, s));
    float cbv = dwe / g_smooth[k];
    if (g_dead[k]) {
        int r = g_rand[k];
        float rr = g_flat[(size_t)r * DIM + d];
        cbv = rr;
        dwe = rr;
    }
    if (OUT_CB + e < osz) out[OUT_CB + e] = cbv;
    if (OUT_DW + e < osz) out[OUT_DW + e] = dwe;
}

// ===========================================================================
extern "C" void kernel_launch(void* const* d_in, const int* in_sizes, int n_in,
                              void* d_out, int out_size) {
    const float* z      = (const float*)d_in[0];
    const float* cb     = (const float*)d_in[1];
    const float* ema_cs = (const float*)d_in[2];
    const float* ema_dw = (const float*)d_in[3];
    float* out = (float*)d_out;
    size_t osz = (size_t)out_size;

    cudaFuncSetAttribute(k_filter, cudaFuncAttributeMaxDynamicSharedMemorySize,
                         SMEM_FILT);

    // NOTE: k_filter is the 3rd launch; k_exact the 4th (ncu capture slot).
    k_cbt<<<256, 256>>>(cb);            // also does scratch init
    k_c2<<<4, 256>>>(cb);
    k_filter<<<1024, 256, SMEM_FILT>>>(z);
    k_exact<<<2048, 256>>>(z, cb);
    k_rng<<<1, 512>>>();
    k_pfx<<<1, 1024>>>();
    k_fill<<<256, 256>>>();
    k_scatter<<<256, 256>>>(z, cb, out, osz);
    k_fin_a<<<1, 1024>>>(ema_cs, out, osz);
    k_fin_b<<<1024, 256>>>(ema_dw, z, out, osz);
}

// round 15
// speedup vs baseline: 1.0106x; 1.0106x over previous
#include <cuda_runtime.h>
#include <cuda_fp16.h>
#include <cstdint>
#include <cstddef>

// Problem constants
#define NROWS 65536   // 64*32*32 flat rows
#define KC    1024    // codes
#define DIM   256     // embedding dim
#define HW    1024    // 32*32

// Output packing (tuple order, all float32)
#define OUT_ZQ   0ull
#define OUT_LOSS 16777216ull
#define OUT_IDX  16777217ull
#define OUT_CB   16842753ull
#define OUT_CS   17104897ull
#define OUT_DW   17105921ull

#define NSLOT  48
#define MARGIN 6e-3f
#define PRUNE_SLACK 6e-4f

// int8 quantization scales (validated R13)
#define INV_SF   (127.0f / 5.5f)
#define CODE_Q   130048.0f                  // 1024*127 (codes in +-1/1024)
#define SCALE    (5.5f / (127.0f * 130048.0f))  // sf * sc

// Scratch (device globals: no allocations allowed)
__device__ float   g_c2[KC];
__device__ int     g_idx[NROWS];
__device__ int     g_counts[KC];
__device__ double  g_loss;
__device__ int     g_rand[KC];
__device__ float   g_smooth[KC];
__device__ int     g_dead[KC];
__device__ int     g_ccnt[NROWS];
__device__ float   g_rmin[NROWS];
__device__ unsigned g_cand[NROWS * NSLOT];   // low16: k, high16: half score bits
__device__ int     g_cbi[16 * 64 * 64];      // int8-packed codebook, tile-major
__device__ float   g_flat[(size_t)NROWS * DIM];  // transposed z (64 MB)
__device__ int     g_off[KC];
__device__ int     g_cursor[KC];
__device__ int     g_rows[NROWS];

// ===========================================================================
#define CP_ASYNC16(dst, src) \
    asm volatile("cp.async.ca.shared.global [%0], [%1], 16;" :: "r"(dst), "l"(src))
#define CP_COMMIT()  asm volatile("cp.async.commit_group;" ::: "memory")
#define CP_WAIT0()   asm volatile("cp.async.wait_group 0;" ::: "memory")

__device__ __forceinline__ uint32_t smem_to_u32(const void* p) {
    uint32_t a;
    asm("{ .reg .u64 t; cvta.to.shared.u64 t, %1; cvt.u32.u64 %0, t; }"
        : "=r"(a) : "l"(p));
    return a;
}

__device__ __forceinline__ int q8(float v, float s) {
    float x = v * s;
    x = fminf(fmaxf(x, -127.0f), 127.0f);
    return __float2int_rn(x);
}

__device__ __forceinline__ unsigned pack_cand(int k, float s) {
    __half h = __float2half_rn(s);
    return (unsigned)k | ((unsigned)__half_as_ushort(h) << 16);
}

// ===========================================================================
// k_cbt: codebook -> int8 tile layout + scratch init.
__global__ void k_cbt(const float* __restrict__ cb) {
    int idx = blockIdx.x * 256 + threadIdx.x;        // 256 blocks -> 65536
    int t = idx >> 12, rem = idx & 4095;
    int d4 = rem >> 6, code = rem & 63;
    const float* src = cb + (size_t)(t * 64 + code) * DIM + 4 * d4;
    int b0 = q8(src[0], CODE_Q) & 255;
    int b1 = q8(src[1], CODE_Q) & 255;
    int b2 = q8(src[2], CODE_Q) & 255;
    int b3 = q8(src[3], CODE_Q) & 255;
    g_cbi[idx] = b0 | (b1 << 8) | (b2 << 16) | (b3 << 24);
    // fused init
    g_ccnt[idx] = 0;                                 // idx spans exactly NROWS
    if (idx < KC) g_counts[idx] = 0;
    if (idx == 0) g_loss = 0.0;
}

// c2[k] = sum_d fl(cb[k][d]^2), sequential in-order fp32 (XLA CPU naive reduce)
__global__ void k_c2(const float* __restrict__ cb) {
    int k = blockIdx.x * blockDim.x + threadIdx.x;
    if (k >= KC) return;
    const float* row = cb + (size_t)k * DIM;
    float s = 0.0f;
    for (int d = 0; d < DIM; ++d) {
        float v = row[d];
        s = __fadd_rn(s, __fmul_rn(v, v));
    }
    g_c2[k] = s;
}

// Exact JAX threefry2x32 for key(1)
__device__ __forceinline__ uint32_t tf_rotl(uint32_t v, int r) {
    return (v << r) | (v >> (32 - r));
}
__global__ void k_rng() {
    int i = threadIdx.x;
    if (i >= 512) return;
    const uint32_t ks0 = 0u, ks1 = 1u, ks2 = 0x1BD11BDBu;
    uint32_t x0 = (uint32_t)i + ks0;
    uint32_t x1 = (uint32_t)(i + 512) + ks1;
    const int ra[4] = {13, 15, 26, 6};
    const int rb[4] = {17, 29, 16, 24};
#define TF_R4(rots) { x0 += x1; x1 = tf_rotl(x1, rots[0]); x1 ^= x0; \
                      x0 += x1; x1 = tf_rotl(x1, rots[1]); x1 ^= x0; \
                      x0 += x1; x1 = tf_rotl(x1, rots[2]); x1 ^= x0; \
                      x0 += x1; x1 = tf_rotl(x1, rots[3]); x1 ^= x0; }
    TF_R4(ra); x0 += ks1; x1 += ks2 + 1u;
    TF_R4(rb); x0 += ks2; x1 += ks0 + 2u;
    TF_R4(ra); x0 += ks0; x1 += ks1 + 3u;
    TF_R4(rb); x0 += ks1; x1 += ks2 + 4u;
    TF_R4(ra); x0 += ks2; x1 += ks0 + 5u;
#undef TF_R4
    g_rand[i]       = (int)(x0 & 0xFFFFu);
    g_rand[i + 512] = (int)(x1 & 0xFFFFu);
}

// ===========================================================================
// k_filter: int8 dp4a approx GEMM, 4x4 register tile, running-min collection
// with packed (k, half-score) candidates + final g_rmin for later pruning.
// CTA = 64 rows, 256 threads, 1024 CTAs.
#define OFF_CODE0 16384
#define OFF_CODE1 33792
#define OFF_C2F   51200
#define SMEM_FILT 55296

__global__ void __launch_bounds__(256, 3) k_filter(const float* __restrict__ z) {
    extern __shared__ char smraw[];
    signed char* s_flat_i8 = (signed char*)smraw;
    const int4*  s_flat_i4 = (const int4*)smraw;
    float* s_c2 = (float*)(smraw + OFF_C2F);
    const uint32_t uS = smem_to_u32(smraw);

    const int tid = threadIdx.x;
    const int g = tid & 15;        // code-group: codes 4g..4g+3 of tile
    const int q = tid >> 4;        // row-group : rows 4q..4q+3

    for (int i = tid; i < KC; i += 256) s_c2[i] = g_c2[i];

    const int n0 = blockIdx.x * 64;
    const int b = n0 >> 10, hw0 = n0 & 1023;
    const float* zb = z + (size_t)b * (DIM * HW) + hw0;

    // ---- stage flat tile quantized int8: byte at [d4*256 + r*4 + (d&3)]
    {
        int r = tid & 63, dchunk = tid >> 6;         // 4 chunks x 64 dims
#pragma unroll
        for (int i = 0; i < 64; ++i) {
            int d = dchunk * 64 + i;
            float v = zb[(size_t)d * HW + r];
            s_flat_i8[(d >> 2) * 256 + r * 4 + (d & 3)] =
                (signed char)q8(v, INV_SF);
        }
    }

    // ---- prologue: stage code tile 0 via cp.async (16KB -> stride-272 rows)
    {
        const int* srcb = g_cbi;
#pragma unroll
        for (int i = 0; i < 4; ++i) {
            int cidx = tid + 256 * i;                // 1024 chunks of 16B
            int d4 = cidx >> 4, seg = cidx & 15;
            CP_ASYNC16(uS + OFF_CODE0 + (uint32_t)(d4 * 272 + seg * 16),
                       srcb + d4 * 64 + seg * 4);
        }
        CP_COMMIT();
    }

    float runm[4];
#pragma unroll
    for (int a = 0; a < 4; ++a) runm[a] = 3.4e38f;

#pragma unroll
    for (int t = 0; t < 16; ++t) {
        CP_WAIT0();
        __syncthreads();
        if (t < 15) {   // stage next tile into other buffer
            const int* srcb = g_cbi + (t + 1) * 4096;
            uint32_t dstb = uS + (((t + 1) & 1) ? OFF_CODE1 : OFF_CODE0);
#pragma unroll
            for (int i = 0; i < 4; ++i) {
                int cidx = tid + 256 * i;
                int d4 = cidx >> 4, seg = cidx & 15;
                CP_ASYNC16(dstb + (uint32_t)(d4 * 272 + seg * 16),
                           srcb + d4 * 64 + seg * 4);
            }
            CP_COMMIT();
        }

        const int4* s_code_i4 =
            (const int4*)(smraw + ((t & 1) ? OFF_CODE1 : OFF_CODE0));

        int acc[4][4];
#pragma unroll
        for (int a = 0; a < 4; ++a)
#pragma unroll
            for (int c = 0; c < 4; ++c) acc[a][c] = 0;

        // 64 d4-steps (4 dims each): exact int32 dp4a, 4 rows x 4 codes
#pragma unroll 16
        for (int d4 = 0; d4 < 64; ++d4) {
            int4 fa = s_flat_i4[d4 * 16 + q];        // rows 4q..4q+3
            int4 cc = s_code_i4[d4 * 17 + g];        // codes 4g..4g+3
            acc[0][0] = __dp4a(fa.x, cc.x, acc[0][0]);
            acc[0][1] = __dp4a(fa.x, cc.y, acc[0][1]);
            acc[0][2] = __dp4a(fa.x, cc.z, acc[0][2]);
            acc[0][3] = __dp4a(fa.x, cc.w, acc[0][3]);
            acc[1][0] = __dp4a(fa.y, cc.x, acc[1][0]);
            acc[1][1] = __dp4a(fa.y, cc.y, acc[1][1]);
            acc[1][2] = __dp4a(fa.y, cc.z, acc[1][2]);
            acc[1][3] = __dp4a(fa.y, cc.w, acc[1][3]);
            acc[2][0] = __dp4a(fa.z, cc.x, acc[2][0]);
            acc[2][1] = __dp4a(fa.z, cc.y, acc[2][1]);
            acc[2][2] = __dp4a(fa.z, cc.z, acc[2][2]);
            acc[2][3] = __dp4a(fa.z, cc.w, acc[2][3]);
            acc[3][0] = __dp4a(fa.w, cc.x, acc[3][0]);
            acc[3][1] = __dp4a(fa.w, cc.y, acc[3][1]);
            acc[3][2] = __dp4a(fa.w, cc.z, acc[3][2]);
            acc[3][3] = __dp4a(fa.w, cc.w, acc[3][3]);
        }

        // ---- epilogue: running-min threshold, collect packed (k, score)
        int kb = t * 64 + 4 * g;
#pragma unroll
        for (int a = 0; a < 4; ++a) {
            float s0 = fmaf(-2.0f * SCALE, (float)acc[a][0], s_c2[kb + 0]);
            float s1 = fmaf(-2.0f * SCALE, (float)acc[a][1], s_c2[kb + 1]);
            float s2 = fmaf(-2.0f * SCALE, (float)acc[a][2], s_c2[kb + 2]);
            float s3 = fmaf(-2.0f * SCALE, (float)acc[a][3], s_c2[kb + 3]);
            float m = fminf(fminf(s0, s1), fminf(s2, s3));
#pragma unroll
            for (int off = 1; off < 16; off <<= 1)
                m = fminf(m, __shfl_xor_sync(0xffffffffu, m, off));
            runm[a] = fminf(runm[a], m);
            float thr = runm[a] + MARGIN;   // >= final threshold -> superset
            int row = n0 + 4 * q + a;
            if (s0 <= thr) { int p = atomicAdd(&g_ccnt[row], 1); if (p < NSLOT) g_cand[row * NSLOT + p] = pack_cand(kb,     s0); }
            if (s1 <= thr) { int p = atomicAdd(&g_ccnt[row], 1); if (p < NSLOT) g_cand[row * NSLOT + p] = pack_cand(kb + 1, s1); }
            if (s2 <= thr) { int p = atomicAdd(&g_ccnt[row], 1); if (p < NSLOT) g_cand[row * NSLOT + p] = pack_cand(kb + 2, s2); }
            if (s3 <= thr) { int p = atomicAdd(&g_ccnt[row], 1); if (p < NSLOT) g_cand[row * NSLOT + p] = pack_cand(kb + 3, s3); }
        }
    }

    // ---- store final row mins for candidate pruning in k_exact
    if (g == 0) {
#pragma unroll
        for (int a = 0; a < 4; ++a)
            g_rmin[n0 + 4 * q + a] = runm[a];
    }
}

// ===========================================================================
// k_exact: block = 32 rows staged in smem; candidates pruned against final
// rmin before chains; f2 fused into first chain. Bitwise sequential fp32
// chains; tie -> lowest k. 2048 x 256.
__global__ void __launch_bounds__(256) k_exact(const float* __restrict__ z,
                                               const float* __restrict__ cb) {
    __shared__ float s_z[DIM * 33];          // [d*33 + r], 33.8 KB
    __shared__ float s_best[8 * 32];
    __shared__ int   s_bk[8 * 32];

    const int tid = threadIdx.x;
    const int n0 = blockIdx.x * 32;
    const int b = n0 >> 10, hw0 = n0 & 1023;
    const float* zb = z + (size_t)b * (DIM * HW) + hw0;

    // stage 32 rows x 256 dims (coalesced gmem, conflict-free smem)
    {
        int r = tid & 31, dg = tid >> 5;     // 8 d-groups
#pragma unroll
        for (int i = 0; i < 32; ++i) {
            int d = dg * 32 + i;
            s_z[d * 33 + r] = zb[(size_t)d * HW + r];
        }
    }
    __syncthreads();

    const int r = tid & 31, slot = tid >> 5;     // slot = warp id

    // write transposed flat copy: warp w -> rows 4w..4w+3
    {
        int w = slot;
#pragma unroll
        for (int rr = 0; rr < 4; ++rr) {
            int row = w * 4 + rr;
            float* dst = &g_flat[(size_t)(n0 + row) * DIM];
#pragma unroll
            for (int c = 0; c < 8; ++c)
                dst[c * 32 + r] = s_z[(c * 32 + r) * 33 + row];
        }
    }

    const int row = n0 + r;
    const int cN = g_ccnt[row];
    const float thr2 = g_rmin[row] + (MARGIN + PRUNE_SLACK);

    float best = 3.4e38f; int bk = 1 << 30;

    if (cN <= NSLOT) {
        float f2 = 0.0f;
        // first pass idx=slot: always run chain (produces f2); use result only
        // if candidate valid and unpruned.
        {
            unsigned pk = (slot < cN) ? g_cand[row * NSLOT + slot] : 0u;
            int k = (int)(pk & 0xFFFFu);
            float sapx = __half2float(__ushort_as_half((unsigned short)(pk >> 16)));
            int use = (slot < cN) && (sapx <= thr2);
            const float4* ck4 = (const float4*)(cb + (size_t)k * DIM);
            float acc = 0.0f, f2a = 0.0f;
#pragma unroll 8
            for (int d4 = 0; d4 < DIM / 4; ++d4) {
                float4 c4 = ck4[d4];
                int d = d4 * 4;
                float v0 = s_z[(d + 0) * 33 + r];
                float v1 = s_z[(d + 1) * 33 + r];
                float v2 = s_z[(d + 2) * 33 + r];
                float v3 = s_z[(d + 3) * 33 + r];
                f2a = __fadd_rn(f2a, __fmul_rn(v0, v0));
                acc = __fmaf_rn(v0, c4.x, acc);
                f2a = __fadd_rn(f2a, __fmul_rn(v1, v1));
                acc = __fmaf_rn(v1, c4.y, acc);
                f2a = __fadd_rn(f2a, __fmul_rn(v2, v2));
                acc = __fmaf_rn(v2, c4.z, acc);
                f2a = __fadd_rn(f2a, __fmul_rn(v3, v3));
                acc = __fmaf_rn(v3, c4.w, acc);
            }
            f2 = f2a;
            if (use) {
                float d2v = __fadd_rn(__fsub_rn(f2, 2.0f * acc), g_c2[k]);
                if (d2v < best || (d2v == best && k < bk)) { best = d2v; bk = k; }
            }
        }
        for (int idx = slot + 8; idx < cN; idx += 8) {
            unsigned pk = g_cand[row * NSLOT + idx];
            int k = (int)(pk & 0xFFFFu);
            float sapx = __half2float(__ushort_as_half((unsigned short)(pk >> 16)));
            if (sapx > thr2) continue;                // pruned: 1 compare
            const float4* ck4 = (const float4*)(cb + (size_t)k * DIM);
            float acc = 0.0f;
#pragma unroll 8
            for (int d4 = 0; d4 < DIM / 4; ++d4) {
                float4 c4 = ck4[d4];
                int d = d4 * 4;
                acc = __fmaf_rn(s_z[(d + 0) * 33 + r], c4.x, acc);
                acc = __fmaf_rn(s_z[(d + 1) * 33 + r], c4.y, acc);
                acc = __fmaf_rn(s_z[(d + 2) * 33 + r], c4.z, acc);
                acc = __fmaf_rn(s_z[(d + 3) * 33 + r], c4.w, acc);
            }
            float d2v = __fadd_rn(__fsub_rn(f2, 2.0f * acc), g_c2[k]);
            if (d2v < best || (d2v == best && k < bk)) { best = d2v; bk = k; }
        }
    } else {
        // overflow fallback: exact full scan (rare)
        float f2 = 0.0f;
        for (int k = slot; k < KC; k += 8) {
            const float4* ck4 = (const float4*)(cb + (size_t)k * DIM);
            float acc = 0.0f, f2a = 0.0f;
#pragma unroll 8
            for (int d4 = 0; d4 < DIM / 4; ++d4) {
                float4 c4 = ck4[d4];
                int d = d4 * 4;
                float v0 = s_z[(d + 0) * 33 + r];
                float v1 = s_z[(d + 1) * 33 + r];
                float v2 = s_z[(d + 2) * 33 + r];
                float v3 = s_z[(d + 3) * 33 + r];
                if (k < 8) {
                    f2a = __fadd_rn(f2a, __fmul_rn(v0, v0));
                    f2a = __fadd_rn(f2a, __fmul_rn(v1, v1));
                    f2a = __fadd_rn(f2a, __fmul_rn(v2, v2));
                    f2a = __fadd_rn(f2a, __fmul_rn(v3, v3));
                }
                acc = __fmaf_rn(v0, c4.x, acc);
                acc = __fmaf_rn(v1, c4.y, acc);
                acc = __fmaf_rn(v2, c4.z, acc);
                acc = __fmaf_rn(v3, c4.w, acc);
            }
            if (k < 8) f2 = f2a;
            float d2v = __fadd_rn(__fsub_rn(f2, 2.0f * acc), g_c2[k]);
            if (d2v < best || (d2v == best && k < bk)) { best = d2v; bk = k; }
        }
    }

    s_best[slot * 32 + r] = best;
    s_bk[slot * 32 + r]   = bk;
    __syncthreads();
    if (tid < 32) {
        float bb = 3.4e38f; int kk = 1 << 30;
#pragma unroll
        for (int s = 0; s < 8; ++s) {
            float v = s_best[s * 32 + tid];
            int   k = s_bk[s * 32 + tid];
            if (v < bb || (v == bb && k < kk)) { bb = v; kk = k; }
        }
        g_idx[n0 + tid] = kk;
        atomicAdd(&g_counts[kk], 1);
    }
}

// ===========================================================================
// k_pfx: exclusive prefix sum of g_counts -> g_off, g_cursor. 1 block x 1024.
__global__ void k_pfx() {
    __shared__ int tmp[KC];
    int k = threadIdx.x;
    int c = g_counts[k];
    tmp[k] = c;
    __syncthreads();
    for (int off = 1; off < KC; off <<= 1) {
        int v = (k >= off) ? tmp[k - off] : 0;
        __syncthreads();
        tmp[k] += v;
        __syncthreads();
    }
    g_off[k] = tmp[k] - c;
    g_cursor[k] = tmp[k] - c;
}

// k_fill: scatter row ids into per-code lists. 256 blocks x 256.
__global__ void k_fill() {
    int n = blockIdx.x * 256 + threadIdx.x;
    int k = g_idx[n];
    int pos = atomicAdd(&g_cursor[k], 1);
    g_rows[pos] = n;
}

// ===========================================================================
// k_scatter: z_q + indices outputs, commit-loss. (dw handled by gather.)
__global__ void __launch_bounds__(256) k_scatter(const float* __restrict__ z,
                                                 const float* __restrict__ cb,
                                                 float* __restrict__ out,
                                                 size_t osz) {
    int n  = blockIdx.x * 256 + threadIdx.x;
    int b  = n >> 10, hw = n & 1023;
    int k  = g_idx[n];
    if (OUT_IDX + (size_t)n < osz) out[OUT_IDX + n] = (float)k;

    const float*  zr   = z  + (size_t)b * DIM * HW + hw;
    float*        orow = out + OUT_ZQ + (size_t)b * DIM * HW + hw;
    const float4* cr   = (const float4*)(cb + (size_t)k * DIM);

    float ls = 0.0f;
#pragma unroll 4
    for (int d4 = 0; d4 < 64; ++d4) {
        float4 qv = cr[d4];
        int d = d4 * 4;
        float z0 = zr[(size_t)(d + 0) * HW];
        float z1 = zr[(size_t)(d + 1) * HW];
        float z2 = zr[(size_t)(d + 2) * HW];
        float z3 = zr[(size_t)(d + 3) * HW];
        orow[(size_t)(d + 0) * HW] = qv.x;
        orow[(size_t)(d + 1) * HW] = qv.y;
        orow[(size_t)(d + 2) * HW] = qv.z;
        orow[(size_t)(d + 3) * HW] = qv.w;
        float e0 = qv.x - z0, e1 = qv.y - z1, e2 = qv.z - z2, e3 = qv.w - z3;
        ls = fmaf(e0, e0, ls); ls = fmaf(e1, e1, ls);
        ls = fmaf(e2, e2, ls); ls = fmaf(e3, e3, ls);
    }

    for (int o = 16; o > 0; o >>= 1) ls += __shfl_down_sync(0xffffffffu, ls, o);
    __shared__ float ws[8];
    int lane = threadIdx.x & 31, w = threadIdx.x >> 5;
    if (lane == 0) ws[w] = ls;
    __syncthreads();
    if (threadIdx.x == 0) {
        float s = 0.0f;
#pragma unroll
        for (int i = 0; i < 8; ++i) s += ws[i];
        atomicAdd(&g_loss, (double)s);
    }
}

// ===========================================================================
__global__ void k_fin_a(const float* __restrict__ ema_cs,
                        float* __restrict__ out, size_t osz) {
    int k = threadIdx.x;
    float cs = __fadd_rn(__fmul_rn(0.99f, ema_cs[k]),
                         __fmul_rn(0.01f, (float)g_counts[k]));
    __shared__ float red[1024];
    red[k] = cs;
    __syncthreads();
    for (int o = 512; o > 0; o >>= 1) {
        if (k < o) red[k] += red[k + o];
        __syncthreads();
    }
    float n = red[0];
    float smv = (cs + 1e-5f) / (n + 1024.0f * 1e-5f) * n;
    g_smooth[k] = smv;
    int dead = cs < 1.0f;
    g_dead[k] = dead;
    if (OUT_CS + (size_t)k < osz) out[OUT_CS + k] = dead ? 1.0f : cs;
    if (k == 0 && OUT_LOSS < osz)
        out[OUT_LOSS] = (float)(0.5 * g_loss / 16777216.0);
}

// ===========================================================================
// k_fin_b: gather dw[k] = sum over rows assigned to k (coalesced g_flat reads)
__global__ void k_fin_b(const float* __restrict__ ema_dw,
                        const float* __restrict__ z,
                        float* __restrict__ out, size_t osz) {
    int k = blockIdx.x;      // 1024
    int d = threadIdx.x;     // 256
    int off = g_off[k], cnt = g_counts[k];
    float s = 0.0f;
    for (int i = 0; i < cnt; ++i) {
        int n = g_rows[off + i];
        s += g_flat[(size_t)n * DIM + d];
    }
    size_t e = (size_t)k * DIM + d;
    float dwe = __fadd_rn(__fmul_rn(0.99f, ema_dw[e]),
                          __fmul_rn(0.01f, s));
    float cbv = dwe / g_smooth[k];
    if (g_dead[k]) {
        int r = g_rand[k];
        float rr = g_flat[(size_t)r * DIM + d];
        cbv = rr;
        dwe = rr;
    }
    if (OUT_CB + e < osz) out[OUT_CB + e] = cbv;
    if (OUT_DW + e < osz) out[OUT_DW + e] = dwe;
}

// ===========================================================================
extern "C" void kernel_launch(void* const* d_in, const int* in_sizes, int n_in,
                              void* d_out, int out_size) {
    const float* z      = (const float*)d_in[0];
    const float* cb     = (const float*)d_in[1];
    const float* ema_cs = (const float*)d_in[2];
    const float* ema_dw = (const float*)d_in[3];
    float* out = (float*)d_out;
    size_t osz = (size_t)out_size;

    cudaFuncSetAttribute(k_filter, cudaFuncAttributeMaxDynamicSharedMemorySize,
                         SMEM_FILT);

    // NOTE: k_filter is the 3rd launch; k_exact the 4th (ncu capture slot).
    k_cbt<<<256, 256>>>(cb);            // also does scratch init
    k_c2<<<4, 256>>>(cb);
    k_filter<<<1024, 256, SMEM_FILT>>>(z);
    k_exact<<<2048, 256>>>(z, cb);
    k_rng<<<1, 512>>>();
    k_pfx<<<1, 1024>>>();
    k_fill<<<256, 256>>>();
    k_scatter<<<256, 256>>>(z, cb, out, osz);
    k_fin_a<<<1, 1024>>>(ema_cs, out, osz);
    k_fin_b<<<1024, 256>>>(ema_dw, z, out, osz);
}

// round 16
// speedup vs baseline: 1.0159x; 1.0052x over previous
#include <cuda_runtime.h>
#include <cuda_fp16.h>
#include <cstdint>
#include <cstddef>

// Problem constants
#define NROWS 65536   // 64*32*32 flat rows
#define KC    1024    // codes
#define DIM   256     // embedding dim
#define HW    1024    // 32*32

// Output packing (tuple order, all float32)
#define OUT_ZQ   0ull
#define OUT_LOSS 16777216ull
#define OUT_IDX  16777217ull
#define OUT_CB   16842753ull
#define OUT_CS   17104897ull
#define OUT_DW   17105921ull

#define NSLOT  128
#define MARGIN 6e-3f
#define PRUNE_SLACK 6e-4f

// int8 quantization scales (validated R13)
#define INV_SF   (127.0f / 5.5f)
#define CODE_Q   130048.0f                  // 1024*127 (codes in +-1/1024)
#define SCALE    (5.5f / (127.0f * 130048.0f))  // sf * sc

// Scratch (device globals: no allocations allowed)
__device__ float   g_c2[KC];
__device__ int     g_idx[NROWS];
__device__ int     g_counts[KC];
__device__ double  g_loss;
__device__ int     g_rand[KC];
__device__ float   g_smooth[KC];
__device__ int     g_dead[KC];
__device__ int     g_ccnt[NROWS];
__device__ float   g_rmin[NROWS];
__device__ unsigned g_cand[(size_t)NROWS * NSLOT]; // low16: k, high16: half score
__device__ int     g_cbi[16 * 64 * 64];      // int8-packed codebook, tile-major
__device__ float   g_flat[(size_t)NROWS * DIM];  // transposed z (64 MB)
__device__ int     g_off[KC];
__device__ int     g_cursor[KC];
__device__ int     g_rows[NROWS];

// ===========================================================================
#define CP_ASYNC16(dst, src) \
    asm volatile("cp.async.ca.shared.global [%0], [%1], 16;" :: "r"(dst), "l"(src))
#define CP_COMMIT()  asm volatile("cp.async.commit_group;" ::: "memory")
#define CP_WAIT0()   asm volatile("cp.async.wait_group 0;" ::: "memory")

__device__ __forceinline__ uint32_t smem_to_u32(const void* p) {
    uint32_t a;
    asm("{ .reg .u64 t; cvta.to.shared.u64 t, %1; cvt.u32.u64 %0, t; }"
        : "=r"(a) : "l"(p));
    return a;
}

__device__ __forceinline__ int q8(float v, float s) {
    float x = v * s;
    x = fminf(fmaxf(x, -127.0f), 127.0f);
    return __float2int_rn(x);
}

__device__ __forceinline__ unsigned pack_cand(int k, float s) {
    __half h = __float2half_rn(s);
    return (unsigned)k | ((unsigned)__half_as_ushort(h) << 16);
}

// ===========================================================================
// k_cbt: codebook -> int8 tile layout + scratch init.
__global__ void k_cbt(const float* __restrict__ cb) {
    int idx = blockIdx.x * 256 + threadIdx.x;        // 256 blocks -> 65536
    int t = idx >> 12, rem = idx & 4095;
    int d4 = rem >> 6, code = rem & 63;
    const float* src = cb + (size_t)(t * 64 + code) * DIM + 4 * d4;
    int b0 = q8(src[0], CODE_Q) & 255;
    int b1 = q8(src[1], CODE_Q) & 255;
    int b2 = q8(src[2], CODE_Q) & 255;
    int b3 = q8(src[3], CODE_Q) & 255;
    g_cbi[idx] = b0 | (b1 << 8) | (b2 << 16) | (b3 << 24);
    // fused init
    g_ccnt[idx] = 0;                                 // idx spans exactly NROWS
    if (idx < KC) g_counts[idx] = 0;
    if (idx == 0) g_loss = 0.0;
}

// c2[k] = sum_d fl(cb[k][d]^2), sequential in-order fp32 (XLA CPU naive reduce)
__global__ void k_c2(const float* __restrict__ cb) {
    int k = blockIdx.x * blockDim.x + threadIdx.x;
    if (k >= KC) return;
    const float* row = cb + (size_t)k * DIM;
    float s = 0.0f;
    for (int d = 0; d < DIM; ++d) {
        float v = row[d];
        s = __fadd_rn(s, __fmul_rn(v, v));
    }
    g_c2[k] = s;
}

// Exact JAX threefry2x32 for key(1)
__device__ __forceinline__ uint32_t tf_rotl(uint32_t v, int r) {
    return (v << r) | (v >> (32 - r));
}
__global__ void k_rng() {
    int i = threadIdx.x;
    if (i >= 512) return;
    const uint32_t ks0 = 0u, ks1 = 1u, ks2 = 0x1BD11BDBu;
    uint32_t x0 = (uint32_t)i + ks0;
    uint32_t x1 = (uint32_t)(i + 512) + ks1;
    const int ra[4] = {13, 15, 26, 6};
    const int rb[4] = {17, 29, 16, 24};
#define TF_R4(rots) { x0 += x1; x1 = tf_rotl(x1, rots[0]); x1 ^= x0; \
                      x0 += x1; x1 = tf_rotl(x1, rots[1]); x1 ^= x0; \
                      x0 += x1; x1 = tf_rotl(x1, rots[2]); x1 ^= x0; \
                      x0 += x1; x1 = tf_rotl(x1, rots[3]); x1 ^= x0; }
    TF_R4(ra); x0 += ks1; x1 += ks2 + 1u;
    TF_R4(rb); x0 += ks2; x1 += ks0 + 2u;
    TF_R4(ra); x0 += ks0; x1 += ks1 + 3u;
    TF_R4(rb); x0 += ks1; x1 += ks2 + 4u;
    TF_R4(ra); x0 += ks2; x1 += ks0 + 5u;
#undef TF_R4
    g_rand[i]       = (int)(x0 & 0xFFFFu);
    g_rand[i + 512] = (int)(x1 & 0xFFFFu);
}

// ===========================================================================
// k_filter: int8 dp4a approx GEMM, 4x4 register tile, running-min collection
// with packed (k, half-score) candidates + final g_rmin for later pruning.
// CTA = 64 rows, 256 threads, 1024 CTAs.
#define OFF_CODE0 16384
#define OFF_CODE1 33792
#define OFF_C2F   51200
#define SMEM_FILT 55296

__global__ void __launch_bounds__(256, 3) k_filter(const float* __restrict__ z) {
    extern __shared__ char smraw[];
    signed char* s_flat_i8 = (signed char*)smraw;
    const int4*  s_flat_i4 = (const int4*)smraw;
    float* s_c2 = (float*)(smraw + OFF_C2F);
    const uint32_t uS = smem_to_u32(smraw);

    const int tid = threadIdx.x;
    const int g = tid & 15;        // code-group: codes 4g..4g+3 of tile
    const int q = tid >> 4;        // row-group : rows 4q..4q+3

    for (int i = tid; i < KC; i += 256) s_c2[i] = g_c2[i];

    const int n0 = blockIdx.x * 64;
    const int b = n0 >> 10, hw0 = n0 & 1023;
    const float* zb = z + (size_t)b * (DIM * HW) + hw0;

    // ---- stage flat tile quantized int8: byte at [d4*256 + r*4 + (d&3)]
    {
        int r = tid & 63, dchunk = tid >> 6;         // 4 chunks x 64 dims
#pragma unroll
        for (int i = 0; i < 64; ++i) {
            int d = dchunk * 64 + i;
            float v = zb[(size_t)d * HW + r];
            s_flat_i8[(d >> 2) * 256 + r * 4 + (d & 3)] =
                (signed char)q8(v, INV_SF);
        }
    }

    // ---- prologue: stage code tile 0 via cp.async (16KB -> stride-272 rows)
    {
        const int* srcb = g_cbi;
#pragma unroll
        for (int i = 0; i < 4; ++i) {
            int cidx = tid + 256 * i;                // 1024 chunks of 16B
            int d4 = cidx >> 4, seg = cidx & 15;
            CP_ASYNC16(uS + OFF_CODE0 + (uint32_t)(d4 * 272 + seg * 16),
                       srcb + d4 * 64 + seg * 4);
        }
        CP_COMMIT();
    }

    float runm[4];
#pragma unroll
    for (int a = 0; a < 4; ++a) runm[a] = 3.4e38f;

#pragma unroll
    for (int t = 0; t < 16; ++t) {
        CP_WAIT0();
        __syncthreads();
        if (t < 15) {   // stage next tile into other buffer
            const int* srcb = g_cbi + (t + 1) * 4096;
            uint32_t dstb = uS + (((t + 1) & 1) ? OFF_CODE1 : OFF_CODE0);
#pragma unroll
            for (int i = 0; i < 4; ++i) {
                int cidx = tid + 256 * i;
                int d4 = cidx >> 4, seg = cidx & 15;
                CP_ASYNC16(dstb + (uint32_t)(d4 * 272 + seg * 16),
                           srcb + d4 * 64 + seg * 4);
            }
            CP_COMMIT();
        }

        const int4* s_code_i4 =
            (const int4*)(smraw + ((t & 1) ? OFF_CODE1 : OFF_CODE0));

        int acc[4][4];
#pragma unroll
        for (int a = 0; a < 4; ++a)
#pragma unroll
            for (int c = 0; c < 4; ++c) acc[a][c] = 0;

        // 64 d4-steps (4 dims each): exact int32 dp4a, 4 rows x 4 codes
#pragma unroll 16
        for (int d4 = 0; d4 < 64; ++d4) {
            int4 fa = s_flat_i4[d4 * 16 + q];        // rows 4q..4q+3
            int4 cc = s_code_i4[d4 * 17 + g];        // codes 4g..4g+3
            acc[0][0] = __dp4a(fa.x, cc.x, acc[0][0]);
            acc[0][1] = __dp4a(fa.x, cc.y, acc[0][1]);
            acc[0][2] = __dp4a(fa.x, cc.z, acc[0][2]);
            acc[0][3] = __dp4a(fa.x, cc.w, acc[0][3]);
            acc[1][0] = __dp4a(fa.y, cc.x, acc[1][0]);
            acc[1][1] = __dp4a(fa.y, cc.y, acc[1][1]);
            acc[1][2] = __dp4a(fa.y, cc.z, acc[1][2]);
            acc[1][3] = __dp4a(fa.y, cc.w, acc[1][3]);
            acc[2][0] = __dp4a(fa.z, cc.x, acc[2][0]);
            acc[2][1] = __dp4a(fa.z, cc.y, acc[2][1]);
            acc[2][2] = __dp4a(fa.z, cc.z, acc[2][2]);
            acc[2][3] = __dp4a(fa.z, cc.w, acc[2][3]);
            acc[3][0] = __dp4a(fa.w, cc.x, acc[3][0]);
            acc[3][1] = __dp4a(fa.w, cc.y, acc[3][1]);
            acc[3][2] = __dp4a(fa.w, cc.z, acc[3][2]);
            acc[3][3] = __dp4a(fa.w, cc.w, acc[3][3]);
        }

        // ---- epilogue: running-min threshold, collect packed (k, score)
        int kb = t * 64 + 4 * g;
#pragma unroll
        for (int a = 0; a < 4; ++a) {
            float s0 = fmaf(-2.0f * SCALE, (float)acc[a][0], s_c2[kb + 0]);
            float s1 = fmaf(-2.0f * SCALE, (float)acc[a][1], s_c2[kb + 1]);
            float s2 = fmaf(-2.0f * SCALE, (float)acc[a][2], s_c2[kb + 2]);
            float s3 = fmaf(-2.0f * SCALE, (float)acc[a][3], s_c2[kb + 3]);
            float m = fminf(fminf(s0, s1), fminf(s2, s3));
#pragma unroll
            for (int off = 1; off < 16; off <<= 1)
                m = fminf(m, __shfl_xor_sync(0xffffffffu, m, off));
            runm[a] = fminf(runm[a], m);
            float thr = runm[a] + MARGIN;   // >= final threshold -> superset
            int row = n0 + 4 * q + a;
            if (s0 <= thr) { int p = atomicAdd(&g_ccnt[row], 1); if (p < NSLOT) g_cand[(size_t)row * NSLOT + p] = pack_cand(kb,     s0); }
            if (s1 <= thr) { int p = atomicAdd(&g_ccnt[row], 1); if (p < NSLOT) g_cand[(size_t)row * NSLOT + p] = pack_cand(kb + 1, s1); }
            if (s2 <= thr) { int p = atomicAdd(&g_ccnt[row], 1); if (p < NSLOT) g_cand[(size_t)row * NSLOT + p] = pack_cand(kb + 2, s2); }
            if (s3 <= thr) { int p = atomicAdd(&g_ccnt[row], 1); if (p < NSLOT) g_cand[(size_t)row * NSLOT + p] = pack_cand(kb + 3, s3); }
        }
    }

    // ---- store final row mins for candidate pruning in k_exact
    if (g == 0) {
#pragma unroll
        for (int a = 0; a < 4; ++a)
            g_rmin[n0 + 4 * q + a] = runm[a];
    }
}

// ===========================================================================
// k_exact: block = 32 rows staged in smem; candidates pruned against final
// rmin before chains; f2 fused into first chain. Bitwise sequential fp32
// chains; tie -> lowest k. 2048 x 256.
__global__ void __launch_bounds__(256) k_exact(const float* __restrict__ z,
                                               const float* __restrict__ cb) {
    __shared__ float s_z[DIM * 33];          // [d*33 + r], 33.8 KB
    __shared__ float s_best[8 * 32];
    __shared__ int   s_bk[8 * 32];

    const int tid = threadIdx.x;
    const int n0 = blockIdx.x * 32;
    const int b = n0 >> 10, hw0 = n0 & 1023;
    const float* zb = z + (size_t)b * (DIM * HW) + hw0;

    // stage 32 rows x 256 dims (coalesced gmem, conflict-free smem)
    {
        int r = tid & 31, dg = tid >> 5;     // 8 d-groups
#pragma unroll
        for (int i = 0; i < 32; ++i) {
            int d = dg * 32 + i;
            s_z[d * 33 + r] = zb[(size_t)d * HW + r];
        }
    }
    __syncthreads();

    const int r = tid & 31, slot = tid >> 5;     // slot = warp id

    // write transposed flat copy: warp w -> rows 4w..4w+3
    {
        int w = slot;
#pragma unroll
        for (int rr = 0; rr < 4; ++rr) {
            int row = w * 4 + rr;
            float* dst = &g_flat[(size_t)(n0 + row) * DIM];
#pragma unroll
            for (int c = 0; c < 8; ++c)
                dst[c * 32 + r] = s_z[(c * 32 + r) * 33 + row];
        }
    }

    const int row = n0 + r;
    const int cN = g_ccnt[row];
    const float thr2 = g_rmin[row] + (MARGIN + PRUNE_SLACK);

    float best = 3.4e38f; int bk = 1 << 30;

    if (cN <= NSLOT) {
        float f2 = 0.0f;
        // first pass idx=slot: always run chain (produces f2); use result only
        // if candidate valid and unpruned.
        {
            unsigned pk = (slot < cN) ? g_cand[(size_t)row * NSLOT + slot] : 0u;
            int k = (int)(pk & 0xFFFFu);
            float sapx = __half2float(__ushort_as_half((unsigned short)(pk >> 16)));
            int use = (slot < cN) && (sapx <= thr2);
            const float4* ck4 = (const float4*)(cb + (size_t)k * DIM);
            float acc = 0.0f, f2a = 0.0f;
#pragma unroll 8
            for (int d4 = 0; d4 < DIM / 4; ++d4) {
                float4 c4 = ck4[d4];
                int d = d4 * 4;
                float v0 = s_z[(d + 0) * 33 + r];
                float v1 = s_z[(d + 1) * 33 + r];
                float v2 = s_z[(d + 2) * 33 + r];
                float v3 = s_z[(d + 3) * 33 + r];
                f2a = __fadd_rn(f2a, __fmul_rn(v0, v0));
                acc = __fmaf_rn(v0, c4.x, acc);
                f2a = __fadd_rn(f2a, __fmul_rn(v1, v1));
                acc = __fmaf_rn(v1, c4.y, acc);
                f2a = __fadd_rn(f2a, __fmul_rn(v2, v2));
                acc = __fmaf_rn(v2, c4.z, acc);
                f2a = __fadd_rn(f2a, __fmul_rn(v3, v3));
                acc = __fmaf_rn(v3, c4.w, acc);
            }
            f2 = f2a;
            if (use) {
                float d2v = __fadd_rn(__fsub_rn(f2, 2.0f * acc), g_c2[k]);
                if (d2v < best || (d2v == best && k < bk)) { best = d2v; bk = k; }
            }
        }
        for (int idx = slot + 8; idx < cN; idx += 8) {
            unsigned pk = g_cand[(size_t)row * NSLOT + idx];
            int k = (int)(pk & 0xFFFFu);
            float sapx = __half2float(__ushort_as_half((unsigned short)(pk >> 16)));
            if (sapx > thr2) continue;                // pruned: 1 compare
            const float4* ck4 = (const float4*)(cb + (size_t)k * DIM);
            float acc = 0.0f;
#pragma unroll 8
            for (int d4 = 0; d4 < DIM / 4; ++d4) {
                float4 c4 = ck4[d4];
                int d = d4 * 4;
                acc = __fmaf_rn(s_z[(d + 0) * 33 + r], c4.x, acc);
                acc = __fmaf_rn(s_z[(d + 1) * 33 + r], c4.y, acc);
                acc = __fmaf_rn(s_z[(d + 2) * 33 + r], c4.z, acc);
                acc = __fmaf_rn(s_z[(d + 3) * 33 + r], c4.w, acc);
            }
            float d2v = __fadd_rn(__fsub_rn(f2, 2.0f * acc), g_c2[k]);
            if (d2v < best || (d2v == best && k < bk)) { best = d2v; bk = k; }
        }
    } else {
        // overflow fallback: exact full scan (unreachable in practice)
        float f2 = 0.0f;
        for (int k = slot; k < KC; k += 8) {
            const float4* ck4 = (const float4*)(cb + (size_t)k * DIM);
            float acc = 0.0f, f2a = 0.0f;
#pragma unroll 8
            for (int d4 = 0; d4 < DIM / 4; ++d4) {
                float4 c4 = ck4[d4];
                int d = d4 * 4;
                float v0 = s_z[(d + 0) * 33 + r];
                float v1 = s_z[(d + 1) * 33 + r];
                float v2 = s_z[(d + 2) * 33 + r];
                float v3 = s_z[(d + 3) * 33 + r];
                if (k < 8) {
                    f2a = __fadd_rn(f2a, __fmul_rn(v0, v0));
                    f2a = __fadd_rn(f2a, __fmul_rn(v1, v1));
                    f2a = __fadd_rn(f2a, __fmul_rn(v2, v2));
                    f2a = __fadd_rn(f2a, __fmul_rn(v3, v3));
                }
                acc = __fmaf_rn(v0, c4.x, acc);
                acc = __fmaf_rn(v1, c4.y, acc);
                acc = __fmaf_rn(v2, c4.z, acc);
                acc = __fmaf_rn(v3, c4.w, acc);
            }
            if (k < 8) f2 = f2a;
            float d2v = __fadd_rn(__fsub_rn(f2, 2.0f * acc), g_c2[k]);
            if (d2v < best || (d2v == best && k < bk)) { best = d2v; bk = k; }
        }
    }

    s_best[slot * 32 + r] = best;
    s_bk[slot * 32 + r]   = bk;
    __syncthreads();
    if (tid < 32) {
        float bb = 3.4e38f; int kk = 1 << 30;
#pragma unroll
        for (int s = 0; s < 8; ++s) {
            float v = s_best[s * 32 + tid];
            int   k = s_bk[s * 32 + tid];
            if (v < bb || (v == bb && k < kk)) { bb = v; kk = k; }
        }
        g_idx[n0 + tid] = kk;
        atomicAdd(&g_counts[kk], 1);
    }
}

// ===========================================================================
// k_pfx: exclusive prefix sum of g_counts -> g_off, g_cursor. 1 block x 1024.
__global__ void k_pfx() {
    __shared__ int tmp[KC];
    int k = threadIdx.x;
    int c = g_counts[k];
    tmp[k] = c;
    __syncthreads();
    for (int off = 1; off < KC; off <<= 1) {
        int v = (k >= off) ? tmp[k - off] : 0;
        __syncthreads();
        tmp[k] += v;
        __syncthreads();
    }
    g_off[k] = tmp[k] - c;
    g_cursor[k] = tmp[k] - c;
}

// k_fill: scatter row ids into per-code lists. 256 blocks x 256.
__global__ void k_fill() {
    int n = blockIdx.x * 256 + threadIdx.x;
    int k = g_idx[n];
    int pos = atomicAdd(&g_cursor[k], 1);
    g_rows[pos] = n;
}

// ===========================================================================
// k_scatter: z_q + indices outputs, commit-loss. (dw handled by gather.)
__global__ void __launch_bounds__(256) k_scatter(const float* __restrict__ z,
                                                 const float* __restrict__ cb,
                                                 float* __restrict__ out,
                                                 size_t osz) {
    int n  = blockIdx.x * 256 + threadIdx.x;
    int b  = n >> 10, hw = n & 1023;
    int k  = g_idx[n];
    if (OUT_IDX + (size_t)n < osz) out[OUT_IDX + n] = (float)k;

    const float*  zr   = z  + (size_t)b * DIM * HW + hw;
    float*        orow = out + OUT_ZQ + (size_t)b * DIM * HW + hw;
    const float4* cr   = (const float4*)(cb + (size_t)k * DIM);

    float ls = 0.0f;
#pragma unroll 4
    for (int d4 = 0; d4 < 64; ++d4) {
        float4 qv = cr[d4];
        int d = d4 * 4;
        float z0 = zr[(size_t)(d + 0) * HW];
        float z1 = zr[(size_t)(d + 1) * HW];
        float z2 = zr[(size_t)(d + 2) * HW];
        float z3 = zr[(size_t)(d + 3) * HW];
        orow[(size_t)(d + 0) * HW] = qv.x;
        orow[(size_t)(d + 1) * HW] = qv.y;
        orow[(size_t)(d + 2) * HW] = qv.z;
        orow[(size_t)(d + 3) * HW] = qv.w;
        float e0 = qv.x - z0, e1 = qv.y - z1, e2 = qv.z - z2, e3 = qv.w - z3;
        ls = fmaf(e0, e0, ls); ls = fmaf(e1, e1, ls);
        ls = fmaf(e2, e2, ls); ls = fmaf(e3, e3, ls);
    }

    for (int o = 16; o > 0; o >>= 1) ls += __shfl_down_sync(0xffffffffu, ls, o);
    __shared__ float ws[8];
    int lane = threadIdx.x & 31, w = threadIdx.x >> 5;
    if (lane == 0) ws[w] = ls;
    __syncthreads();
    if (threadIdx.x == 0) {
        float s = 0.0f;
#pragma unroll
        for (int i = 0; i < 8; ++i) s += ws[i];
        atomicAdd(&g_loss, (double)s);
    }
}

// ===========================================================================
__global__ void k_fin_a(const float* __restrict__ ema_cs,
                        float* __restrict__ out, size_t osz) {
    int k = threadIdx.x;
    float cs = __fadd_rn(__fmul_rn(0.99f, ema_cs[k]),
                         __fmul_rn(0.01f, (float)g_counts[k]));
    __shared__ float red[1024];
    red[k] = cs;
    __syncthreads();
    for (int o = 512; o > 0; o >>= 1) {
        if (k < o) red[k] += red[k + o];
        __syncthreads();
    }
    float n = red[0];
    float smv = (cs + 1e-5f) / (n + 1024.0f * 1e-5f) * n;
    g_smooth[k] = smv;
    int dead = cs < 1.0f;
    g_dead[k] = dead;
    if (OUT_CS + (size_t)k < osz) out[OUT_CS + k] = dead ? 1.0f : cs;
    if (k == 0 && OUT_LOSS < osz)
        out[OUT_LOSS] = (float)(0.5 * g_loss / 16777216.0);
}

// ===========================================================================
// k_fin_b: gather dw[k] = sum over rows assigned to k (coalesced g_flat reads)
__global__ void k_fin_b(const float* __restrict__ ema_dw,
                        const float* __restrict__ z,
                        float* __restrict__ out, size_t osz) {
    int k = blockIdx.x;      // 1024
    int d = threadIdx.x;     // 256
    int off = g_off[k], cnt = g_counts[k];
    float s = 0.0f;
    for (int i = 0; i < cnt; ++i) {
        int n = g_rows[off + i];
        s += g_flat[(size_t)n * DIM + d];
    }
    size_t e = (size_t)k * DIM + d;
    float dwe = __fadd_rn(__fmul_rn(0.99f, ema_dw[e]),
                          __fmul_rn(0.01f, s));
    float cbv = dwe / g_smooth[k];
    if (g_dead[k]) {
        int r = g_rand[k];
        float rr = g_flat[(size_t)r * DIM + d];
        cbv = rr;
        dwe = rr;
    }
    if (OUT_CB + e < osz) out[OUT_CB + e] = cbv;
    if (OUT_DW + e < osz) out[OUT_DW + e] = dwe;
}

// ===========================================================================
extern "C" void kernel_launch(void* const* d_in, const int* in_sizes, int n_in,
                              void* d_out, int out_size) {
    const float* z      = (const float*)d_in[0];
    const float* cb     = (const float*)d_in[1];
    const float* ema_cs = (const float*)d_in[2];
    const float* ema_dw = (const float*)d_in[3];
    float* out = (float*)d_out;
    size_t osz = (size_t)out_size;

    cudaFuncSetAttribute(k_filter, cudaFuncAttributeMaxDynamicSharedMemorySize,
                         SMEM_FILT);

    // NOTE: k_filter is the 3rd launch; k_exact the 4th (ncu capture slot).
    k_cbt<<<256, 256>>>(cb);            // also does scratch init
    k_c2<<<4, 256>>>(cb);
    k_filter<<<1024, 256, SMEM_FILT>>>(z);
    k_exact<<<2048, 256>>>(z, cb);
    k_rng<<<1, 512>>>();
    k_pfx<<<1, 1024>>>();
    k_fill<<<256, 256>>>();
    k_scatter<<<256, 256>>>(z, cb, out, osz);
    k_fin_a<<<1, 1024>>>(ema_cs, out, osz);
    k_fin_b<<<1024, 256>>>(ema_dw, z, out, osz);
}

// round 17
// speedup vs baseline: 1.1382x; 1.1204x over previous
#include <cuda_runtime.h>
#include <cuda_fp16.h>
#include <cstdint>
#include <cstddef>

// Problem constants
#define NROWS 65536   // 64*32*32 flat rows
#define KC    1024    // codes
#define DIM   256     // embedding dim
#define HW    1024    // 32*32

// Output packing (tuple order, all float32)
#define OUT_ZQ   0ull
#define OUT_LOSS 16777216ull
#define OUT_IDX  16777217ull
#define OUT_CB   16842753ull
#define OUT_CS   17104897ull
#define OUT_DW   17105921ull

#define NSLOT  128
#define MARGIN 6e-3f
#define PRUNE_SLACK 6e-4f

// int8 quantization scales (validated R13)
#define INV_SF   (127.0f / 5.5f)
#define CODE_Q   130048.0f                  // 1024*127 (codes in +-1/1024)
#define SCALE    (5.5f / (127.0f * 130048.0f))  // sf * sc

// Scratch (device globals: no allocations allowed)
__device__ float   g_c2[KC];
__device__ int     g_idx[NROWS];
__device__ int     g_counts[KC];
__device__ double  g_loss;
__device__ int     g_rand[KC];
__device__ float   g_smooth[KC];
__device__ int     g_dead[KC];
__device__ int     g_ccnt[NROWS];
__device__ float   g_rmin[NROWS];
__device__ unsigned g_cand[(size_t)NROWS * NSLOT]; // low16: k, high16: half score
__device__ int     g_cbi[16 * 64 * 64];      // int8-packed codebook, tile-major
__device__ float   g_flat[(size_t)NROWS * DIM];  // transposed z (64 MB)
__device__ int     g_off[KC];
__device__ int     g_cursor[KC];
__device__ int     g_rows[NROWS];

// ===========================================================================
#define CP_ASYNC16(dst, src) \
    asm volatile("cp.async.ca.shared.global [%0], [%1], 16;" :: "r"(dst), "l"(src))
#define CP_COMMIT()  asm volatile("cp.async.commit_group;" ::: "memory")
#define CP_WAIT0()   asm volatile("cp.async.wait_group 0;" ::: "memory")

__device__ __forceinline__ uint32_t smem_to_u32(const void* p) {
    uint32_t a;
    asm("{ .reg .u64 t; cvta.to.shared.u64 t, %1; cvt.u32.u64 %0, t; }"
        : "=r"(a) : "l"(p));
    return a;
}

__device__ __forceinline__ int q8(float v, float s) {
    float x = v * s;
    x = fminf(fmaxf(x, -127.0f), 127.0f);
    return __float2int_rn(x);
}

__device__ __forceinline__ unsigned pack_cand(int k, float s) {
    __half h = __float2half_rn(s);
    return (unsigned)k | ((unsigned)__half_as_ushort(h) << 16);
}

// ===========================================================================
// k_cbt: codebook -> int8 tile layout + scratch init.
__global__ void k_cbt(const float* __restrict__ cb) {
    int idx = blockIdx.x * 256 + threadIdx.x;        // 256 blocks -> 65536
    int t = idx >> 12, rem = idx & 4095;
    int d4 = rem >> 6, code = rem & 63;
    const float* src = cb + (size_t)(t * 64 + code) * DIM + 4 * d4;
    int b0 = q8(src[0], CODE_Q) & 255;
    int b1 = q8(src[1], CODE_Q) & 255;
    int b2 = q8(src[2], CODE_Q) & 255;
    int b3 = q8(src[3], CODE_Q) & 255;
    g_cbi[idx] = b0 | (b1 << 8) | (b2 << 16) | (b3 << 24);
    // fused init
    g_ccnt[idx] = 0;                                 // idx spans exactly NROWS
    if (idx < KC) g_counts[idx] = 0;
    if (idx == 0) g_loss = 0.0;
}

// c2[k] = sum_d fl(cb[k][d]^2), sequential in-order fp32 (XLA CPU naive reduce)
__global__ void k_c2(const float* __restrict__ cb) {
    int k = blockIdx.x * blockDim.x + threadIdx.x;
    if (k >= KC) return;
    const float* row = cb + (size_t)k * DIM;
    float s = 0.0f;
    for (int d = 0; d < DIM; ++d) {
        float v = row[d];
        s = __fadd_rn(s, __fmul_rn(v, v));
    }
    g_c2[k] = s;
}

// Exact JAX threefry2x32 for key(1)
__device__ __forceinline__ uint32_t tf_rotl(uint32_t v, int r) {
    return (v << r) | (v >> (32 - r));
}
__global__ void k_rng() {
    int i = threadIdx.x;
    if (i >= 512) return;
    const uint32_t ks0 = 0u, ks1 = 1u, ks2 = 0x1BD11BDBu;
    uint32_t x0 = (uint32_t)i + ks0;
    uint32_t x1 = (uint32_t)(i + 512) + ks1;
    const int ra[4] = {13, 15, 26, 6};
    const int rb[4] = {17, 29, 16, 24};
#define TF_R4(rots) { x0 += x1; x1 = tf_rotl(x1, rots[0]); x1 ^= x0; \
                      x0 += x1; x1 = tf_rotl(x1, rots[1]); x1 ^= x0; \
                      x0 += x1; x1 = tf_rotl(x1, rots[2]); x1 ^= x0; \
                      x0 += x1; x1 = tf_rotl(x1, rots[3]); x1 ^= x0; }
    TF_R4(ra); x0 += ks1; x1 += ks2 + 1u;
    TF_R4(rb); x0 += ks2; x1 += ks0 + 2u;
    TF_R4(ra); x0 += ks0; x1 += ks1 + 3u;
    TF_R4(rb); x0 += ks1; x1 += ks2 + 4u;
    TF_R4(ra); x0 += ks2; x1 += ks0 + 5u;
#undef TF_R4
    g_rand[i]       = (int)(x0 & 0xFFFFu);
    g_rand[i + 512] = (int)(x1 & 0xFFFFu);
}

// ===========================================================================
// k_filter: int8 dp4a approx GEMM, 4x4 register tile, running-min collection
// with packed (k, half-score) candidates + final g_rmin for pruning.
// CTA = 64 rows, 256 threads, 1024 CTAs.  (R14/R16 config, measured ~343us)
#define OFF_CODE0 16384
#define OFF_CODE1 33792
#define OFF_C2F   51200
#define SMEM_FILT 55296

__global__ void __launch_bounds__(256, 3) k_filter(const float* __restrict__ z) {
    extern __shared__ char smraw[];
    signed char* s_flat_i8 = (signed char*)smraw;
    const int4*  s_flat_i4 = (const int4*)smraw;
    float* s_c2 = (float*)(smraw + OFF_C2F);
    const uint32_t uS = smem_to_u32(smraw);

    const int tid = threadIdx.x;
    const int g = tid & 15;        // code-group: codes 4g..4g+3 of tile
    const int q = tid >> 4;        // row-group : rows 4q..4q+3

    for (int i = tid; i < KC; i += 256) s_c2[i] = g_c2[i];

    const int n0 = blockIdx.x * 64;
    const int b = n0 >> 10, hw0 = n0 & 1023;
    const float* zb = z + (size_t)b * (DIM * HW) + hw0;

    // ---- stage flat tile quantized int8: byte at [d4*256 + r*4 + (d&3)]
    {
        int r = tid & 63, dchunk = tid >> 6;         // 4 chunks x 64 dims
#pragma unroll
        for (int i = 0; i < 64; ++i) {
            int d = dchunk * 64 + i;
            float v = zb[(size_t)d * HW + r];
            s_flat_i8[(d >> 2) * 256 + r * 4 + (d & 3)] =
                (signed char)q8(v, INV_SF);
        }
    }

    // ---- prologue: stage code tile 0 via cp.async (16KB -> stride-272 rows)
    {
        const int* srcb = g_cbi;
#pragma unroll
        for (int i = 0; i < 4; ++i) {
            int cidx = tid + 256 * i;                // 1024 chunks of 16B
            int d4 = cidx >> 4, seg = cidx & 15;
            CP_ASYNC16(uS + OFF_CODE0 + (uint32_t)(d4 * 272 + seg * 16),
                       srcb + d4 * 64 + seg * 4);
        }
        CP_COMMIT();
    }

    float runm[4];
#pragma unroll
    for (int a = 0; a < 4; ++a) runm[a] = 3.4e38f;

#pragma unroll
    for (int t = 0; t < 16; ++t) {
        CP_WAIT0();
        __syncthreads();
        if (t < 15) {   // stage next tile into other buffer
            const int* srcb = g_cbi + (t + 1) * 4096;
            uint32_t dstb = uS + (((t + 1) & 1) ? OFF_CODE1 : OFF_CODE0);
#pragma unroll
            for (int i = 0; i < 4; ++i) {
                int cidx = tid + 256 * i;
                int d4 = cidx >> 4, seg = cidx & 15;
                CP_ASYNC16(dstb + (uint32_t)(d4 * 272 + seg * 16),
                           srcb + d4 * 64 + seg * 4);
            }
            CP_COMMIT();
        }

        const int4* s_code_i4 =
            (const int4*)(smraw + ((t & 1) ? OFF_CODE1 : OFF_CODE0));

        int acc[4][4];
#pragma unroll
        for (int a = 0; a < 4; ++a)
#pragma unroll
            for (int c = 0; c < 4; ++c) acc[a][c] = 0;

        // 64 d4-steps (4 dims each): exact int32 dp4a, 4 rows x 4 codes
#pragma unroll 16
        for (int d4 = 0; d4 < 64; ++d4) {
            int4 fa = s_flat_i4[d4 * 16 + q];        // rows 4q..4q+3
            int4 cc = s_code_i4[d4 * 17 + g];        // codes 4g..4g+3
            acc[0][0] = __dp4a(fa.x, cc.x, acc[0][0]);
            acc[0][1] = __dp4a(fa.x, cc.y, acc[0][1]);
            acc[0][2] = __dp4a(fa.x, cc.z, acc[0][2]);
            acc[0][3] = __dp4a(fa.x, cc.w, acc[0][3]);
            acc[1][0] = __dp4a(fa.y, cc.x, acc[1][0]);
            acc[1][1] = __dp4a(fa.y, cc.y, acc[1][1]);
            acc[1][2] = __dp4a(fa.y, cc.z, acc[1][2]);
            acc[1][3] = __dp4a(fa.y, cc.w, acc[1][3]);
            acc[2][0] = __dp4a(fa.z, cc.x, acc[2][0]);
            acc[2][1] = __dp4a(fa.z, cc.y, acc[2][1]);
            acc[2][2] = __dp4a(fa.z, cc.z, acc[2][2]);
            acc[2][3] = __dp4a(fa.z, cc.w, acc[2][3]);
            acc[3][0] = __dp4a(fa.w, cc.x, acc[3][0]);
            acc[3][1] = __dp4a(fa.w, cc.y, acc[3][1]);
            acc[3][2] = __dp4a(fa.w, cc.z, acc[3][2]);
            acc[3][3] = __dp4a(fa.w, cc.w, acc[3][3]);
        }

        // ---- epilogue: running-min threshold, collect packed (k, score)
        int kb = t * 64 + 4 * g;
#pragma unroll
        for (int a = 0; a < 4; ++a) {
            float s0 = fmaf(-2.0f * SCALE, (float)acc[a][0], s_c2[kb + 0]);
            float s1 = fmaf(-2.0f * SCALE, (float)acc[a][1], s_c2[kb + 1]);
            float s2 = fmaf(-2.0f * SCALE, (float)acc[a][2], s_c2[kb + 2]);
            float s3 = fmaf(-2.0f * SCALE, (float)acc[a][3], s_c2[kb + 3]);
            float m = fminf(fminf(s0, s1), fminf(s2, s3));
#pragma unroll
            for (int off = 1; off < 16; off <<= 1)
                m = fminf(m, __shfl_xor_sync(0xffffffffu, m, off));
            runm[a] = fminf(runm[a], m);
            float thr = runm[a] + MARGIN;   // >= final threshold -> superset
            int row = n0 + 4 * q + a;
            if (s0 <= thr) { int p = atomicAdd(&g_ccnt[row], 1); if (p < NSLOT) g_cand[(size_t)row * NSLOT + p] = pack_cand(kb,     s0); }
            if (s1 <= thr) { int p = atomicAdd(&g_ccnt[row], 1); if (p < NSLOT) g_cand[(size_t)row * NSLOT + p] = pack_cand(kb + 1, s1); }
            if (s2 <= thr) { int p = atomicAdd(&g_ccnt[row], 1); if (p < NSLOT) g_cand[(size_t)row * NSLOT + p] = pack_cand(kb + 2, s2); }
            if (s3 <= thr) { int p = atomicAdd(&g_ccnt[row], 1); if (p < NSLOT) g_cand[(size_t)row * NSLOT + p] = pack_cand(kb + 3, s3); }
        }
    }

    // ---- store final row mins for candidate pruning in k_exact
    if (g == 0) {
#pragma unroll
        for (int a = 0; a < 4; ++a)
            g_rmin[n0 + 4 * q + a] = runm[a];
    }
}

// ===========================================================================
// k_exact: R13 structure (measured 100us): separate f2 chain, candidate loop
// from idx=slot, + cheap score-based prune. Bitwise sequential fp32 chains;
// tie -> lowest k. 2048 x 256.
__global__ void __launch_bounds__(256) k_exact(const float* __restrict__ z,
                                               const float* __restrict__ cb) {
    __shared__ float s_z[DIM * 33];          // [d*33 + r], 33.8 KB
    __shared__ float s_best[8 * 32];
    __shared__ int   s_bk[8 * 32];

    const int tid = threadIdx.x;
    const int n0 = blockIdx.x * 32;
    const int b = n0 >> 10, hw0 = n0 & 1023;
    const float* zb = z + (size_t)b * (DIM * HW) + hw0;

    // stage 32 rows x 256 dims (coalesced gmem, conflict-free smem)
    {
        int r = tid & 31, dg = tid >> 5;     // 8 d-groups
#pragma unroll
        for (int i = 0; i < 32; ++i) {
            int d = dg * 32 + i;
            s_z[d * 33 + r] = zb[(size_t)d * HW + r];
        }
    }
    __syncthreads();

    const int r = tid & 31, slot = tid >> 5;     // slot = warp id

    // write transposed flat copy: warp w -> rows 4w..4w+3
    {
        int w = slot;
#pragma unroll
        for (int rr = 0; rr < 4; ++rr) {
            int row = w * 4 + rr;
            float* dst = &g_flat[(size_t)(n0 + row) * DIM];
#pragma unroll
            for (int c = 0; c < 8; ++c)
                dst[c * 32 + r] = s_z[(c * 32 + r) * 33 + row];
        }
    }

    const int row = n0 + r;
    const int cN = g_ccnt[row];
    const float thr2 = g_rmin[row] + (MARGIN + PRUNE_SLACK);

    // f2: bitwise sequential chain (same bits as reference order)
    float f2 = 0.0f;
    for (int d = 0; d < DIM; ++d) {
        float fv = s_z[d * 33 + r];
        f2 = __fadd_rn(f2, __fmul_rn(fv, fv));
    }

    float best = 3.4e38f; int bk = 1 << 30;

    if (cN <= NSLOT) {
        for (int idx = slot; idx < cN; idx += 8) {
            unsigned pk = g_cand[(size_t)row * NSLOT + idx];
            int k = (int)(pk & 0xFFFFu);
            float sapx = __half2float(__ushort_as_half((unsigned short)(pk >> 16)));
            if (sapx > thr2) continue;                // pruned: 1 compare
            const float4* ck4 = (const float4*)(cb + (size_t)k * DIM);
            float acc = 0.0f;
#pragma unroll 8
            for (int d4 = 0; d4 < DIM / 4; ++d4) {
                float4 c4 = ck4[d4];
                int d = d4 * 4;
                acc = __fmaf_rn(s_z[(d + 0) * 33 + r], c4.x, acc);
                acc = __fmaf_rn(s_z[(d + 1) * 33 + r], c4.y, acc);
                acc = __fmaf_rn(s_z[(d + 2) * 33 + r], c4.z, acc);
                acc = __fmaf_rn(s_z[(d + 3) * 33 + r], c4.w, acc);
            }
            float d2v = __fadd_rn(__fsub_rn(f2, 2.0f * acc), g_c2[k]);
            if (d2v < best || (d2v == best && k < bk)) { best = d2v; bk = k; }
        }
    } else {
        // overflow fallback: exact full scan (unreachable in practice)
        for (int k = slot; k < KC; k += 8) {
            const float4* ck4 = (const float4*)(cb + (size_t)k * DIM);
            float acc = 0.0f;
#pragma unroll 8
            for (int d4 = 0; d4 < DIM / 4; ++d4) {
                float4 c4 = ck4[d4];
                int d = d4 * 4;
                acc = __fmaf_rn(s_z[(d + 0) * 33 + r], c4.x, acc);
                acc = __fmaf_rn(s_z[(d + 1) * 33 + r], c4.y, acc);
                acc = __fmaf_rn(s_z[(d + 2) * 33 + r], c4.z, acc);
                acc = __fmaf_rn(s_z[(d + 3) * 33 + r], c4.w, acc);
            }
            float d2v = __fadd_rn(__fsub_rn(f2, 2.0f * acc), g_c2[k]);
            if (d2v < best || (d2v == best && k < bk)) { best = d2v; bk = k; }
        }
    }

    s_best[slot * 32 + r] = best;
    s_bk[slot * 32 + r]   = bk;
    __syncthreads();
    if (tid < 32) {
        float bb = 3.4e38f; int kk = 1 << 30;
#pragma unroll
        for (int s = 0; s < 8; ++s) {
            float v = s_best[s * 32 + tid];
            int   k = s_bk[s * 32 + tid];
            if (v < bb || (v == bb && k < kk)) { bb = v; kk = k; }
        }
        g_idx[n0 + tid] = kk;
        atomicAdd(&g_counts[kk], 1);
    }
}

// ===========================================================================
// k_pfx: exclusive prefix sum of g_counts -> g_off, g_cursor. 1 block x 1024.
__global__ void k_pfx() {
    __shared__ int tmp[KC];
    int k = threadIdx.x;
    int c = g_counts[k];
    tmp[k] = c;
    __syncthreads();
    for (int off = 1; off < KC; off <<= 1) {
        int v = (k >= off) ? tmp[k - off] : 0;
        __syncthreads();
        tmp[k] += v;
        __syncthreads();
    }
    g_off[k] = tmp[k] - c;
    g_cursor[k] = tmp[k] - c;
}

// k_fill: scatter row ids into per-code lists. 256 blocks x 256.
__global__ void k_fill() {
    int n = blockIdx.x * 256 + threadIdx.x;
    int k = g_idx[n];
    int pos = atomicAdd(&g_cursor[k], 1);
    g_rows[pos] = n;
}

// ===========================================================================
// k_scatter: z_q + indices outputs, commit-loss. (dw handled by gather.)
__global__ void __launch_bounds__(256) k_scatter(const float* __restrict__ z,
                                                 const float* __restrict__ cb,
                                                 float* __restrict__ out,
                                                 size_t osz) {
    int n  = blockIdx.x * 256 + threadIdx.x;
    int b  = n >> 10, hw = n & 1023;
    int k  = g_idx[n];
    if (OUT_IDX + (size_t)n < osz) out[OUT_IDX + n] = (float)k;

    const float*  zr   = z  + (size_t)b * DIM * HW + hw;
    float*        orow = out + OUT_ZQ + (size_t)b * DIM * HW + hw;
    const float4* cr   = (const float4*)(cb + (size_t)k * DIM);

    float ls = 0.0f;
#pragma unroll 4
    for (int d4 = 0; d4 < 64; ++d4) {
        float4 qv = cr[d4];
        int d = d4 * 4;
        float z0 = zr[(size_t)(d + 0) * HW];
        float z1 = zr[(size_t)(d + 1) * HW];
        float z2 = zr[(size_t)(d + 2) * HW];
        float z3 = zr[(size_t)(d + 3) * HW];
        orow[(size_t)(d + 0) * HW] = qv.x;
        orow[(size_t)(d + 1) * HW] = qv.y;
        orow[(size_t)(d + 2) * HW] = qv.z;
        orow[(size_t)(d + 3) * HW] = qv.w;
        float e0 = qv.x - z0, e1 = qv.y - z1, e2 = qv.z - z2, e3 = qv.w - z3;
        ls = fmaf(e0, e0, ls); ls = fmaf(e1, e1, ls);
        ls = fmaf(e2, e2, ls); ls = fmaf(e3, e3, ls);
    }

    for (int o = 16; o > 0; o >>= 1) ls += __shfl_down_sync(0xffffffffu, ls, o);
    __shared__ float ws[8];
    int lane = threadIdx.x & 31, w = threadIdx.x >> 5;
    if (lane == 0) ws[w] = ls;
    __syncthreads();
    if (threadIdx.x == 0) {
        float s = 0.0f;
#pragma unroll
        for (int i = 0; i < 8; ++i) s += ws[i];
        atomicAdd(&g_loss, (double)s);
    }
}

// ===========================================================================
__global__ void k_fin_a(const float* __restrict__ ema_cs,
                        float* __restrict__ out, size_t osz) {
    int k = threadIdx.x;
    float cs = __fadd_rn(__fmul_rn(0.99f, ema_cs[k]),
                         __fmul_rn(0.01f, (float)g_counts[k]));
    __shared__ float red[1024];
    red[k] = cs;
    __syncthreads();
    for (int o = 512; o > 0; o >>= 1) {
        if (k < o) red[k] += red[k + o];
        __syncthreads();
    }
    float n = red[0];
    float smv = (cs + 1e-5f) / (n + 1024.0f * 1e-5f) * n;
    g_smooth[k] = smv;
    int dead = cs < 1.0f;
    g_dead[k] = dead;
    if (OUT_CS + (size_t)k < osz) out[OUT_CS + k] = dead ? 1.0f : cs;
    if (k == 0 && OUT_LOSS < osz)
        out[OUT_LOSS] = (float)(0.5 * g_loss / 16777216.0);
}

// ===========================================================================
// k_fin_b: gather dw[k] = sum over rows assigned to k (coalesced g_flat reads)
__global__ void k_fin_b(const float* __restrict__ ema_dw,
                        const float* __restrict__ z,
                        float* __restrict__ out, size_t osz) {
    int k = blockIdx.x;      // 1024
    int d = threadIdx.x;     // 256
    int off = g_off[k], cnt = g_counts[k];
    float s = 0.0f;
    for (int i = 0; i < cnt; ++i) {
        int n = g_rows[off + i];
        s += g_flat[(size_t)n * DIM + d];
    }
    size_t e = (size_t)k * DIM + d;
    float dwe = __fadd_rn(__fmul_rn(0.99f, ema_dw[e]),
                          __fmul_rn(0.01f, s));
    float cbv = dwe / g_smooth[k];
    if (g_dead[k]) {
        int r = g_rand[k];
        float rr = g_flat[(size_t)r * DIM + d];
        cbv = rr;
        dwe = rr;
    }
    if (OUT_CB + e < osz) out[OUT_CB + e] = cbv;
    if (OUT_DW + e < osz) out[OUT_DW + e] = dwe;
}

// ===========================================================================
extern "C" void kernel_launch(void* const* d_in, const int* in_sizes, int n_in,
                              void* d_out, int out_size) {
    const float* z      = (const float*)d_in[0];
    const float* cb     = (const float*)d_in[1];
    const float* ema_cs = (const float*)d_in[2];
    const float* ema_dw = (const float*)d_in[3];
    float* out = (float*)d_out;
    size_t osz = (size_t)out_size;

    cudaFuncSetAttribute(k_filter, cudaFuncAttributeMaxDynamicSharedMemorySize,
                         SMEM_FILT);

    // NOTE: k_filter is the 3rd launch; k_exact the 4th (ncu capture slot).
    k_cbt<<<256, 256>>>(cb);            // also does scratch init
    k_c2<<<4, 256>>>(cb);
    k_filter<<<1024, 256, SMEM_FILT>>>(z);
    k_exact<<<2048, 256>>>(z, cb);
    k_rng<<<1, 512>>>();
    k_pfx<<<1, 1024>>>();
    k_fill<<<256, 256>>>();
    k_scatter<<<256, 256>>>(z, cb, out, osz);
    k_fin_a<<<1, 1024>>>(ema_cs, out, osz);
    k_fin_b<<<1024, 256>>>(ema_dw, z, out, osz);
}